// round 2
// baseline (speedup 1.0000x reference)
#include <cuda_runtime.h>
#include <math.h>
#include <stdint.h>

#define T_TOK 8192
#define DM 1024
#define DFF 4096
#define NE 8
#define MAXROWS 17408   // 2*8192 + 8*128 padding
#define MT 128

// ---------------- scratch (static device globals; no allocations) ----------------
__device__ float g_h[(size_t)MAXROWS * DFF];    // GEMM1 output (gelu(h)), fp32
__device__ float g_y2[(size_t)MAXROWS * DM];    // GEMM2 output (gated), fp32
__device__ int   g_counts[NE];
__device__ int   g_cursor[NE];
__device__ int   g_off[NE];
__device__ int   g_tiles[NE];
__device__ int   g_topk_e[T_TOK * 2];
__device__ float g_topk_p[T_TOK * 2];
__device__ int   g_rowmap[MAXROWS];
__device__ float g_rowgate[MAXROWS];
__device__ int   g_pos[T_TOK * 2];

// ---------------- helpers ----------------
__device__ __forceinline__ uint32_t f2tf(float f) {
    uint32_t u;
    asm("cvt.rna.tf32.f32 %0, %1;" : "=r"(u) : "f"(f));
    return u;
}

__device__ __forceinline__ float4 cvt4(float4 v) {
    float4 w;
    w.x = __uint_as_float(f2tf(v.x));
    w.y = __uint_as_float(f2tf(v.y));
    w.z = __uint_as_float(f2tf(v.z));
    w.w = __uint_as_float(f2tf(v.w));
    return w;
}

// jax.nn.gelu default: approximate=True (tanh form)
__device__ __forceinline__ float gelu_f(float v) {
    float c = 0.7978845608028654f * (v + 0.044715f * v * v * v);
    return 0.5f * v * (1.0f + tanhf(c));
}

// ---------------- K0: zero counters ----------------
__global__ void zero_kernel() {
    int i = threadIdx.x;
    if (i < NE) { g_counts[i] = 0; g_cursor[i] = 0; }
}

// ---------------- K1: router (1 warp per token) ----------------
__global__ void __launch_bounds__(256) router_kernel(
    const float* __restrict__ x, const float* __restrict__ rw, const float* __restrict__ rb)
{
    int t = (blockIdx.x * blockDim.x + threadIdx.x) >> 5;
    int lane = threadIdx.x & 31;
    if (t >= T_TOK) return;
    const float* xr = x + (size_t)t * DM;
    float acc[NE];
    #pragma unroll
    for (int e = 0; e < NE; e++) acc[e] = 0.f;
    for (int k = lane; k < DM; k += 32) {
        float xv = xr[k];
        const float4* w4 = (const float4*)(rw + (size_t)k * NE);
        float4 wa = w4[0], wb = w4[1];
        acc[0] += xv * wa.x; acc[1] += xv * wa.y; acc[2] += xv * wa.z; acc[3] += xv * wa.w;
        acc[4] += xv * wb.x; acc[5] += xv * wb.y; acc[6] += xv * wb.z; acc[7] += xv * wb.w;
    }
    #pragma unroll
    for (int off = 16; off > 0; off >>= 1) {
        #pragma unroll
        for (int e = 0; e < NE; e++) acc[e] += __shfl_down_sync(0xffffffffu, acc[e], off);
    }
    if (lane == 0) {
        float logit[NE], m = -1e30f;
        #pragma unroll
        for (int e = 0; e < NE; e++) { logit[e] = acc[e] + rb[e]; m = fmaxf(m, logit[e]); }
        float s = 0.f, p[NE];
        #pragma unroll
        for (int e = 0; e < NE; e++) { p[e] = expf(logit[e] - m); s += p[e]; }
        float inv = 1.0f / s;
        #pragma unroll
        for (int e = 0; e < NE; e++) p[e] *= inv;
        int i1 = 0;
        #pragma unroll
        for (int e = 1; e < NE; e++) if (p[e] > p[i1]) i1 = e;
        int i2 = (i1 == 0) ? 1 : 0;
        #pragma unroll
        for (int e = 0; e < NE; e++) { if (e == i1) continue; if (p[e] > p[i2]) i2 = e; }
        g_topk_e[t * 2] = i1; g_topk_e[t * 2 + 1] = i2;
        g_topk_p[t * 2] = p[i1]; g_topk_p[t * 2 + 1] = p[i2];
        atomicAdd(&g_counts[i1], 1);
        atomicAdd(&g_counts[i2], 1);
    }
}

// ---------------- K2: offsets + pad rowmap ----------------
__global__ void offsets_kernel() {
    __shared__ int soff[NE], scnt[NE], stiles[NE];
    if (threadIdx.x == 0) {
        int off = 0;
        for (int e = 0; e < NE; e++) {
            int c = g_counts[e];
            int tiles = (c + MT - 1) / MT;
            g_off[e] = off; g_tiles[e] = tiles;
            soff[e] = off; scnt[e] = c; stiles[e] = tiles;
            off += tiles * MT;
        }
    }
    __syncthreads();
    for (int e = 0; e < NE; e++) {
        int start = soff[e] + scnt[e];
        int end = soff[e] + stiles[e] * MT;
        for (int r = start + (int)threadIdx.x; r < end; r += blockDim.x) {
            g_rowmap[r] = -1;
            g_rowgate[r] = 0.f;
        }
    }
}

// ---------------- K3: slot assignment ----------------
__global__ void assign_kernel() {
    int t = blockIdx.x * blockDim.x + threadIdx.x;
    if (t >= T_TOK) return;
    #pragma unroll
    for (int k = 0; k < 2; k++) {
        int e = g_topk_e[t * 2 + k];
        int slot = atomicAdd(&g_cursor[e], 1);
        int r = g_off[e] + slot;
        g_rowmap[r] = t;
        g_rowgate[r] = g_topk_p[t * 2 + k];
        g_pos[t * 2 + k] = r;
    }
}

// ---------------- K4/K5: tf32 GEMM (PHASE 1: x@w1+gelu->h, PHASE 2: h@w2 *gate ->y2) ----------------
template <int PHASE>
__global__ void __launch_bounds__(256) moe_gemm_kernel(
    const float* __restrict__ Ain, const float* __restrict__ W, const float* __restrict__ bias)
{
    constexpr int KTOT = (PHASE == 1) ? DM : DFF;
    constexpr int NTOT = (PHASE == 1) ? DFF : DM;

    const int e = blockIdx.y >> 6;
    const int mt = blockIdx.y & 63;
    if (mt >= g_tiles[e]) return;
    const int nt = blockIdx.x;
    const int row0 = g_off[e] + mt * MT;

    __shared__ __align__(16) float sbuf[8832];  // As[128][36] + Bs[32][132]; reused as Cs[128][68]
    __shared__ int rmap[MT];
    float* As = sbuf;
    float* Bs = sbuf + 128 * 36;

    const int tid = threadIdx.x;
    const int warp = tid >> 5;
    const int lane = tid & 31;
    const int g = lane >> 2;
    const int l = lane & 3;
    const int wm = warp >> 1;   // 0..3 : 32 rows each
    const int wn = warp & 1;    // 0..1 : 64 cols each

    if (PHASE == 1) {
        if (tid < MT) rmap[tid] = g_rowmap[row0 + tid];
    }
    __syncthreads();

    float acc[2][8][4];
    #pragma unroll
    for (int a = 0; a < 2; a++)
        #pragma unroll
        for (int b = 0; b < 8; b++)
            #pragma unroll
            for (int c = 0; c < 4; c++) acc[a][b][c] = 0.f;

    const float* Wb = W + (size_t)e * KTOT * NTOT + (size_t)nt * 128;

    for (int kt = 0; kt < KTOT; kt += 32) {
        // stage A tile [128 x 32] (tf32-rounded)
        #pragma unroll
        for (int i = 0; i < 4; i++) {
            int idx4 = tid + i * 256;
            int r = idx4 >> 3;
            int kc = (idx4 & 7) << 2;
            float4 v;
            if (PHASE == 1) {
                int src = rmap[r];
                if (src >= 0) v = *(const float4*)(Ain + (size_t)src * DM + kt + kc);
                else v = make_float4(0.f, 0.f, 0.f, 0.f);
            } else {
                v = *(const float4*)(g_h + (size_t)(row0 + r) * DFF + kt + kc);
            }
            *(float4*)&As[r * 36 + kc] = cvt4(v);
        }
        // stage B tile [32 x 128]
        #pragma unroll
        for (int i = 0; i < 4; i++) {
            int idx4 = tid + i * 256;
            int kr = idx4 >> 5;
            int nc = (idx4 & 31) << 2;
            float4 v = *(const float4*)(Wb + (size_t)(kt + kr) * NTOT + nc);
            *(float4*)&Bs[kr * 132 + nc] = cvt4(v);
        }
        __syncthreads();

        #pragma unroll
        for (int ks = 0; ks < 4; ks++) {
            const int k0 = ks * 8;
            uint32_t afr[2][4];
            #pragma unroll
            for (int im = 0; im < 2; im++) {
                int mb = wm * 32 + im * 16;
                afr[im][0] = __float_as_uint(As[(mb + g) * 36 + k0 + l]);
                afr[im][1] = __float_as_uint(As[(mb + g + 8) * 36 + k0 + l]);
                afr[im][2] = __float_as_uint(As[(mb + g) * 36 + k0 + l + 4]);
                afr[im][3] = __float_as_uint(As[(mb + g + 8) * 36 + k0 + l + 4]);
            }
            #pragma unroll
            for (int in_ = 0; in_ < 8; in_++) {
                int nb = wn * 64 + in_ * 8;
                uint32_t b0 = __float_as_uint(Bs[(k0 + l) * 132 + nb + g]);
                uint32_t b1 = __float_as_uint(Bs[(k0 + l + 4) * 132 + nb + g]);
                #pragma unroll
                for (int im = 0; im < 2; im++) {
                    asm volatile(
                        "mma.sync.aligned.m16n8k8.row.col.f32.tf32.tf32.f32 "
                        "{%0,%1,%2,%3},{%4,%5,%6,%7},{%8,%9},{%0,%1,%2,%3};"
                        : "+f"(acc[im][in_][0]), "+f"(acc[im][in_][1]),
                          "+f"(acc[im][in_][2]), "+f"(acc[im][in_][3])
                        : "r"(afr[im][0]), "r"(afr[im][1]), "r"(afr[im][2]), "r"(afr[im][3]),
                          "r"(b0), "r"(b1));
                }
            }
        }
        __syncthreads();
    }

    // epilogue: stage through smem per 64-col half for coalesced global stores
    float* Cs = sbuf;  // [128][68]
    const float* biasE = bias + (size_t)e * NTOT;
    for (int half = 0; half < 2; half++) {
        __syncthreads();
        if (wn == half) {
            #pragma unroll
            for (int im = 0; im < 2; im++)
                #pragma unroll
                for (int in_ = 0; in_ < 8; in_++)
                    #pragma unroll
                    for (int r = 0; r < 4; r++) {
                        int rr = wm * 32 + im * 16 + g + ((r >> 1) << 3);
                        int cc = in_ * 8 + 2 * l + (r & 1);
                        Cs[rr * 68 + cc] = acc[im][in_][r];
                    }
        }
        __syncthreads();
        #pragma unroll
        for (int i = 0; i < 8; i++) {
            int idx4 = tid + i * 256;
            int r = idx4 >> 4;
            int c4 = (idx4 & 15) << 2;
            float4 v = *(float4*)&Cs[r * 68 + c4];
            int col = nt * 128 + half * 64 + c4;
            float4 bv = *(const float4*)&biasE[col];
            if (PHASE == 1) {
                v.x = gelu_f(v.x + bv.x);
                v.y = gelu_f(v.y + bv.y);
                v.z = gelu_f(v.z + bv.z);
                v.w = gelu_f(v.w + bv.w);
                *(float4*)&g_h[(size_t)(row0 + r) * DFF + col] = v;
            } else {
                float gate = g_rowgate[row0 + r];
                v.x = gate * (v.x + bv.x);
                v.y = gate * (v.y + bv.y);
                v.z = gate * (v.z + bv.z);
                v.w = gate * (v.w + bv.w);
                *(float4*)&g_y2[(size_t)(row0 + r) * DM + col] = v;
            }
        }
    }
}

// ---------------- K6: combine + residual + LayerNorm ----------------
__global__ void __launch_bounds__(256) combine_ln_kernel(
    const float* __restrict__ x, const float* __restrict__ gamma,
    const float* __restrict__ beta, float* __restrict__ out, int out_size)
{
    int t = blockIdx.x;
    int tid = threadIdx.x;
    __shared__ float red[18];
    int p0 = g_pos[t * 2], p1 = g_pos[t * 2 + 1];
    float4 xv = ((const float4*)(x + (size_t)t * DM))[tid];
    float4 av = ((const float4*)(g_y2 + (size_t)p0 * DM))[tid];
    float4 bv = ((const float4*)(g_y2 + (size_t)p1 * DM))[tid];
    float4 y;
    y.x = xv.x + av.x + bv.x;
    y.y = xv.y + av.y + bv.y;
    y.z = xv.z + av.z + bv.z;
    y.w = xv.w + av.w + bv.w;
    float s  = y.x + y.y + y.z + y.w;
    float ss = y.x * y.x + y.y * y.y + y.z * y.z + y.w * y.w;
    #pragma unroll
    for (int o = 16; o > 0; o >>= 1) {
        s  += __shfl_down_sync(0xffffffffu, s, o);
        ss += __shfl_down_sync(0xffffffffu, ss, o);
    }
    int warp = tid >> 5, lane = tid & 31;
    if (lane == 0) { red[warp] = s; red[8 + warp] = ss; }
    __syncthreads();
    if (tid == 0) {
        float S = 0.f, SS = 0.f;
        #pragma unroll
        for (int w = 0; w < 8; w++) { S += red[w]; SS += red[8 + w]; }
        red[16] = S; red[17] = SS;
    }
    __syncthreads();
    float mu = red[16] * (1.0f / 1024.0f);
    float var = red[17] * (1.0f / 1024.0f) - mu * mu;
    float rs = rsqrtf(var + 1e-5f);
    float4 g4 = ((const float4*)gamma)[tid];
    float4 b4 = ((const float4*)beta)[tid];
    float4 z;
    z.x = (y.x - mu) * rs * g4.x + b4.x;
    z.y = (y.y - mu) * rs * g4.y + b4.y;
    z.z = (y.z - mu) * rs * g4.z + b4.z;
    z.w = (y.w - mu) * rs * g4.w + b4.w;
    if ((size_t)t * DM + (size_t)tid * 4 + 4 <= (size_t)out_size)
        ((float4*)(out + (size_t)t * DM))[tid] = z;
}

// ---------------- K7: "selected" export tail (if harness expects it) ----------------
__global__ void selected_kernel(float* __restrict__ out, int extras) {
    int i = blockIdx.x * blockDim.x + threadIdx.x;
    if (i < extras) {
        float v = (i < NE && g_counts[i] > 0) ? 1.0f : 0.0f;
        out[(size_t)T_TOK * DM + i] = v;
    }
}

// ---------------- launch ----------------
extern "C" void kernel_launch(void* const* d_in, const int* in_sizes, int n_in,
                              void* d_out, int out_size)
{
    const float* x     = (const float*)d_in[0];
    const float* rw    = (const float*)d_in[1];
    const float* rb    = (const float*)d_in[2];
    const float* w1    = (const float*)d_in[3];
    const float* b1    = (const float*)d_in[4];
    const float* w2    = (const float*)d_in[5];
    const float* b2    = (const float*)d_in[6];
    const float* gamma = (const float*)d_in[7];
    const float* beta  = (const float*)d_in[8];
    float* out = (float*)d_out;

    zero_kernel<<<1, 32>>>();
    router_kernel<<<T_TOK / 8, 256>>>(x, rw, rb);
    offsets_kernel<<<1, 256>>>();
    assign_kernel<<<T_TOK / 256, 256>>>();
    moe_gemm_kernel<1><<<dim3(DFF / 128, NE * 64), 256>>>(x, w1, b1);
    moe_gemm_kernel<2><<<dim3(DM / 128, NE * 64), 256>>>(x, w2, b2);
    combine_ln_kernel<<<T_TOK, 256>>>(x, gamma, beta, out, out_size);
    int extras = out_size - T_TOK * DM;
    if (extras > 0) {
        selected_kernel<<<(extras + 255) / 256, 256>>>(out, extras);
    }
}

// round 6
// speedup vs baseline: 1.4526x; 1.4526x over previous
#include <cuda_runtime.h>
#include <math.h>
#include <stdint.h>

#define T_TOK 8192
#define DM 1024
#define DFF 4096
#define NE 8
#define MAXROWS 17408   // 2*8192 + 8*128 padding
#define MT 128

#define STAGE_F 8832            // floats per pipeline stage: A 128*36 + B 32*132
#define SMEM_DYN (512 + 2 * STAGE_F * 4)

// ---------------- scratch (static device globals; no allocations) ----------------
__device__ float g_h[(size_t)MAXROWS * DFF];    // GEMM1 output (gelu(h)), fp32
__device__ float g_y2[(size_t)MAXROWS * DM];    // GEMM2 output (gated), fp32
__device__ int   g_counts[NE];
__device__ int   g_cursor[NE];
__device__ int   g_off[NE];
__device__ int   g_tiles[NE];
__device__ int   g_topk_e[T_TOK * 2];
__device__ float g_topk_p[T_TOK * 2];
__device__ int   g_rowmap[MAXROWS];
__device__ float g_rowgate[MAXROWS];
__device__ int   g_pos[T_TOK * 2];

// ---------------- helpers ----------------
__device__ __forceinline__ void cp_async16(uint32_t dst, const void* src, int srcbytes) {
    asm volatile("cp.async.cg.shared.global [%0], [%1], 16, %2;\n"
                 :: "r"(dst), "l"(src), "r"(srcbytes));
}

// jax.nn.gelu default: approximate=True (tanh form)
__device__ __forceinline__ float gelu_f(float v) {
    float c = 0.7978845608028654f * (v + 0.044715f * v * v * v);
    return 0.5f * v * (1.0f + tanhf(c));
}

// ---------------- K0: zero counters ----------------
__global__ void zero_kernel() {
    int i = threadIdx.x;
    if (i < NE) { g_counts[i] = 0; g_cursor[i] = 0; }
}

// ---------------- K1: router (1 warp per token) ----------------
__global__ void __launch_bounds__(256) router_kernel(
    const float* __restrict__ x, const float* __restrict__ rw, const float* __restrict__ rb)
{
    int t = (blockIdx.x * blockDim.x + threadIdx.x) >> 5;
    int lane = threadIdx.x & 31;
    if (t >= T_TOK) return;
    const float* xr = x + (size_t)t * DM;
    float acc[NE];
    #pragma unroll
    for (int e = 0; e < NE; e++) acc[e] = 0.f;
    for (int k = lane; k < DM; k += 32) {
        float xv = xr[k];
        const float4* w4 = (const float4*)(rw + (size_t)k * NE);
        float4 wa = w4[0], wb = w4[1];
        acc[0] += xv * wa.x; acc[1] += xv * wa.y; acc[2] += xv * wa.z; acc[3] += xv * wa.w;
        acc[4] += xv * wb.x; acc[5] += xv * wb.y; acc[6] += xv * wb.z; acc[7] += xv * wb.w;
    }
    #pragma unroll
    for (int off = 16; off > 0; off >>= 1) {
        #pragma unroll
        for (int e = 0; e < NE; e++) acc[e] += __shfl_down_sync(0xffffffffu, acc[e], off);
    }
    if (lane == 0) {
        float logit[NE], m = -1e30f;
        #pragma unroll
        for (int e = 0; e < NE; e++) { logit[e] = acc[e] + rb[e]; m = fmaxf(m, logit[e]); }
        float s = 0.f, p[NE];
        #pragma unroll
        for (int e = 0; e < NE; e++) { p[e] = expf(logit[e] - m); s += p[e]; }
        float inv = 1.0f / s;
        #pragma unroll
        for (int e = 0; e < NE; e++) p[e] *= inv;
        int i1 = 0;
        #pragma unroll
        for (int e = 1; e < NE; e++) if (p[e] > p[i1]) i1 = e;
        int i2 = (i1 == 0) ? 1 : 0;
        #pragma unroll
        for (int e = 0; e < NE; e++) { if (e == i1) continue; if (p[e] > p[i2]) i2 = e; }
        g_topk_e[t * 2] = i1; g_topk_e[t * 2 + 1] = i2;
        g_topk_p[t * 2] = p[i1]; g_topk_p[t * 2 + 1] = p[i2];
        atomicAdd(&g_counts[i1], 1);
        atomicAdd(&g_counts[i2], 1);
    }
}

// ---------------- K2: offsets + pad rowmap ----------------
__global__ void offsets_kernel() {
    __shared__ int soff[NE], scnt[NE], stiles[NE];
    if (threadIdx.x == 0) {
        int off = 0;
        for (int e = 0; e < NE; e++) {
            int c = g_counts[e];
            int tiles = (c + MT - 1) / MT;
            g_off[e] = off; g_tiles[e] = tiles;
            soff[e] = off; scnt[e] = c; stiles[e] = tiles;
            off += tiles * MT;
        }
    }
    __syncthreads();
    for (int e = 0; e < NE; e++) {
        int start = soff[e] + scnt[e];
        int end = soff[e] + stiles[e] * MT;
        for (int r = start + (int)threadIdx.x; r < end; r += blockDim.x) {
            g_rowmap[r] = -1;
            g_rowgate[r] = 0.f;
        }
    }
}

// ---------------- K3: slot assignment ----------------
__global__ void assign_kernel() {
    int t = blockIdx.x * blockDim.x + threadIdx.x;
    if (t >= T_TOK) return;
    #pragma unroll
    for (int k = 0; k < 2; k++) {
        int e = g_topk_e[t * 2 + k];
        int slot = atomicAdd(&g_cursor[e], 1);
        int r = g_off[e] + slot;
        g_rowmap[r] = t;
        g_rowgate[r] = g_topk_p[t * 2 + k];
        g_pos[t * 2 + k] = r;
    }
}

// ---------------- K4/K5: tf32 GEMM, cp.async double-buffered ----------------
// PHASE 1: gather(x) @ w1 + b1 -> gelu -> g_h      (K=1024, N=4096)
// PHASE 2: g_h @ w2 + b2, *gate -> g_y2            (K=4096, N=1024)
template <int PHASE>
__global__ void __launch_bounds__(256, 2) moe_gemm_kernel(
    const float* __restrict__ Ain, const float* __restrict__ W, const float* __restrict__ bias)
{
    constexpr int KTOT = (PHASE == 1) ? DM : DFF;
    constexpr int NTOT = (PHASE == 1) ? DFF : DM;

    const int e = blockIdx.y >> 6;
    const int mt = blockIdx.y & 63;
    if (mt >= g_tiles[e]) return;
    const int nt = blockIdx.x;
    const int row0 = g_off[e] + mt * MT;

    extern __shared__ __align__(16) char dynbuf[];
    int*   rmap = (int*)dynbuf;               // 128 ints (512 B)
    float* sbuf = (float*)(dynbuf + 512);     // 2 stages of [A 128x36 | B 32x132]

    const int tid = threadIdx.x;
    const int warp = tid >> 5;
    const int lane = tid & 31;
    const int g = lane >> 2;
    const int l = lane & 3;
    const int wm = warp >> 1;   // 0..3 : 32 rows each
    const int wn = warp & 1;    // 0..1 : 64 cols each

    if (PHASE == 1) {
        if (tid < MT) rmap[tid] = g_rowmap[row0 + tid];
    }
    __syncthreads();

    const float* Wb = W + (size_t)e * KTOT * NTOT + (size_t)nt * 128;

    // per-thread cp.async chunk setup (4 A chunks + 4 B chunks, 16B each)
    const char* asrc[4];
    const char* bsrc[4];
    uint32_t aoff[4], boff[4];
    int asz[4];
    #pragma unroll
    for (int i = 0; i < 4; i++) {
        int idx = tid + i * 256;
        int r  = idx >> 3;
        int kc = (idx & 7) << 2;
        if (PHASE == 1) {
            int s = rmap[r];
            asz[i]  = (s >= 0) ? 16 : 0;
            asrc[i] = (const char*)(Ain + ((s >= 0) ? (size_t)s * DM : 0) + kc);
        } else {
            asz[i]  = 16;
            asrc[i] = (const char*)(g_h + (size_t)(row0 + r) * DFF + kc);
        }
        aoff[i] = (uint32_t)(r * 36 + kc) * 4u;

        int kr = idx >> 5;
        int nc = (idx & 31) << 2;
        bsrc[i] = (const char*)(Wb + (size_t)kr * NTOT + nc);
        boff[i] = (uint32_t)(4608 + kr * 132 + nc) * 4u;
    }

    uint32_t sb0 = (uint32_t)__cvta_generic_to_shared(sbuf);
    uint32_t sb1 = sb0 + STAGE_F * 4;

#define GEMM_ISSUE(KT, SBASE)                                                              \
    do {                                                                                    \
        _Pragma("unroll")                                                                   \
        for (int i = 0; i < 4; i++)                                                         \
            cp_async16((SBASE) + aoff[i], asrc[i] + (size_t)(KT) * 4, asz[i]);              \
        _Pragma("unroll")                                                                   \
        for (int i = 0; i < 4; i++)                                                         \
            cp_async16((SBASE) + boff[i], bsrc[i] + (size_t)(KT) * NTOT * 4, 16);           \
        asm volatile("cp.async.commit_group;\n" ::: "memory");                              \
    } while (0)

    float acc[2][8][4];
    #pragma unroll
    for (int a = 0; a < 2; a++)
        #pragma unroll
        for (int b = 0; b < 8; b++)
            #pragma unroll
            for (int c = 0; c < 4; c++) acc[a][b][c] = 0.f;

    GEMM_ISSUE(0, sb0);

    int buf = 0;
    for (int kt = 0; kt < KTOT; kt += 32, buf ^= 1) {
        if (kt + 32 < KTOT) {
            GEMM_ISSUE(kt + 32, buf ? sb0 : sb1);
            asm volatile("cp.async.wait_group 1;\n" ::: "memory");
        } else {
            asm volatile("cp.async.wait_group 0;\n" ::: "memory");
        }
        __syncthreads();

        const float* As = sbuf + buf * STAGE_F;
        const float* Bs = As + 4608;

        #pragma unroll
        for (int ks = 0; ks < 4; ks++) {
            const int k0 = ks * 8;
            uint32_t afr[2][4];
            #pragma unroll
            for (int im = 0; im < 2; im++) {
                int mb = wm * 32 + im * 16;
                afr[im][0] = __float_as_uint(As[(mb + g) * 36 + k0 + l]);
                afr[im][1] = __float_as_uint(As[(mb + g + 8) * 36 + k0 + l]);
                afr[im][2] = __float_as_uint(As[(mb + g) * 36 + k0 + l + 4]);
                afr[im][3] = __float_as_uint(As[(mb + g + 8) * 36 + k0 + l + 4]);
            }
            #pragma unroll
            for (int in_ = 0; in_ < 8; in_++) {
                int nb = wn * 64 + in_ * 8;
                uint32_t b0 = __float_as_uint(Bs[(k0 + l) * 132 + nb + g]);
                uint32_t b1 = __float_as_uint(Bs[(k0 + l + 4) * 132 + nb + g]);
                #pragma unroll
                for (int im = 0; im < 2; im++) {
                    asm volatile(
                        "mma.sync.aligned.m16n8k8.row.col.f32.tf32.tf32.f32 "
                        "{%0,%1,%2,%3},{%4,%5,%6,%7},{%8,%9},{%0,%1,%2,%3};"
                        : "+f"(acc[im][in_][0]), "+f"(acc[im][in_][1]),
                          "+f"(acc[im][in_][2]), "+f"(acc[im][in_][3])
                        : "r"(afr[im][0]), "r"(afr[im][1]), "r"(afr[im][2]), "r"(afr[im][3]),
                          "r"(b0), "r"(b1));
                }
            }
        }
        __syncthreads();
    }
#undef GEMM_ISSUE

    // epilogue: stage through smem per 64-col half for coalesced global stores
    float* Cs = sbuf;  // reuse stage 0: [128][68]
    const float* biasE = bias + (size_t)e * NTOT;
    for (int half = 0; half < 2; half++) {
        __syncthreads();
        if (wn == half) {
            #pragma unroll
            for (int im = 0; im < 2; im++)
                #pragma unroll
                for (int in_ = 0; in_ < 8; in_++)
                    #pragma unroll
                    for (int r = 0; r < 4; r++) {
                        int rr = wm * 32 + im * 16 + g + ((r >> 1) << 3);
                        int cc = in_ * 8 + 2 * l + (r & 1);
                        Cs[rr * 68 + cc] = acc[im][in_][r];
                    }
        }
        __syncthreads();
        #pragma unroll
        for (int i = 0; i < 8; i++) {
            int idx4 = tid + i * 256;
            int r = idx4 >> 4;
            int c4 = (idx4 & 15) << 2;
            float4 v = *(float4*)&Cs[r * 68 + c4];
            int col = nt * 128 + half * 64 + c4;
            float4 bv = *(const float4*)&biasE[col];
            if (PHASE == 1) {
                v.x = gelu_f(v.x + bv.x);
                v.y = gelu_f(v.y + bv.y);
                v.z = gelu_f(v.z + bv.z);
                v.w = gelu_f(v.w + bv.w);
                *(float4*)&g_h[(size_t)(row0 + r) * DFF + col] = v;
            } else {
                float gate = g_rowgate[row0 + r];
                v.x = gate * (v.x + bv.x);
                v.y = gate * (v.y + bv.y);
                v.z = gate * (v.z + bv.z);
                v.w = gate * (v.w + bv.w);
                *(float4*)&g_y2[(size_t)(row0 + r) * DM + col] = v;
            }
        }
    }
}

// ---------------- K6: combine + residual + LayerNorm ----------------
__global__ void __launch_bounds__(256) combine_ln_kernel(
    const float* __restrict__ x, const float* __restrict__ gamma,
    const float* __restrict__ beta, float* __restrict__ out, int out_size)
{
    int t = blockIdx.x;
    int tid = threadIdx.x;
    __shared__ float red[18];
    int p0 = g_pos[t * 2], p1 = g_pos[t * 2 + 1];
    float4 xv = ((const float4*)(x + (size_t)t * DM))[tid];
    float4 av = ((const float4*)(g_y2 + (size_t)p0 * DM))[tid];
    float4 bv = ((const float4*)(g_y2 + (size_t)p1 * DM))[tid];
    float4 y;
    y.x = xv.x + av.x + bv.x;
    y.y = xv.y + av.y + bv.y;
    y.z = xv.z + av.z + bv.z;
    y.w = xv.w + av.w + bv.w;
    float s  = y.x + y.y + y.z + y.w;
    float ss = y.x * y.x + y.y * y.y + y.z * y.z + y.w * y.w;
    #pragma unroll
    for (int o = 16; o > 0; o >>= 1) {
        s  += __shfl_down_sync(0xffffffffu, s, o);
        ss += __shfl_down_sync(0xffffffffu, ss, o);
    }
    int warp = tid >> 5, lane = tid & 31;
    if (lane == 0) { red[warp] = s; red[8 + warp] = ss; }
    __syncthreads();
    if (tid == 0) {
        float S = 0.f, SS = 0.f;
        #pragma unroll
        for (int w = 0; w < 8; w++) { S += red[w]; SS += red[8 + w]; }
        red[16] = S; red[17] = SS;
    }
    __syncthreads();
    float mu = red[16] * (1.0f / 1024.0f);
    float var = red[17] * (1.0f / 1024.0f) - mu * mu;
    float rs = rsqrtf(var + 1e-5f);
    float4 g4 = ((const float4*)gamma)[tid];
    float4 b4 = ((const float4*)beta)[tid];
    float4 z;
    z.x = (y.x - mu) * rs * g4.x + b4.x;
    z.y = (y.y - mu) * rs * g4.y + b4.y;
    z.z = (y.z - mu) * rs * g4.z + b4.z;
    z.w = (y.w - mu) * rs * g4.w + b4.w;
    if ((size_t)t * DM + (size_t)tid * 4 + 4 <= (size_t)out_size)
        ((float4*)(out + (size_t)t * DM))[tid] = z;
}

// ---------------- K7: "selected" export tail (if harness expects it) ----------------
__global__ void selected_kernel(float* __restrict__ out, int extras) {
    int i = blockIdx.x * blockDim.x + threadIdx.x;
    if (i < extras) {
        float v = (i < NE && g_counts[i] > 0) ? 1.0f : 0.0f;
        out[(size_t)T_TOK * DM + i] = v;
    }
}

// ---------------- launch ----------------
extern "C" void kernel_launch(void* const* d_in, const int* in_sizes, int n_in,
                              void* d_out, int out_size)
{
    const float* x     = (const float*)d_in[0];
    const float* rw    = (const float*)d_in[1];
    const float* rb    = (const float*)d_in[2];
    const float* w1    = (const float*)d_in[3];
    const float* b1    = (const float*)d_in[4];
    const float* w2    = (const float*)d_in[5];
    const float* b2    = (const float*)d_in[6];
    const float* gamma = (const float*)d_in[7];
    const float* beta  = (const float*)d_in[8];
    float* out = (float*)d_out;

    cudaFuncSetAttribute(moe_gemm_kernel<1>, cudaFuncAttributeMaxDynamicSharedMemorySize, SMEM_DYN);
    cudaFuncSetAttribute(moe_gemm_kernel<2>, cudaFuncAttributeMaxDynamicSharedMemorySize, SMEM_DYN);

    zero_kernel<<<1, 32>>>();
    router_kernel<<<T_TOK / 8, 256>>>(x, rw, rb);
    offsets_kernel<<<1, 256>>>();
    assign_kernel<<<T_TOK / 256, 256>>>();
    moe_gemm_kernel<1><<<dim3(DFF / 128, NE * 64), 256, SMEM_DYN>>>(x, w1, b1);
    moe_gemm_kernel<2><<<dim3(DM / 128, NE * 64), 256, SMEM_DYN>>>(x, w2, b2);
    combine_ln_kernel<<<T_TOK, 256>>>(x, gamma, beta, out, out_size);
    int extras = out_size - T_TOK * DM;
    if (extras > 0) {
        selected_kernel<<<(extras + 255) / 256, 256>>>(out, extras);
    }
}

// round 10
// speedup vs baseline: 1.4874x; 1.0239x over previous
#include <cuda_runtime.h>
#include <math.h>
#include <stdint.h>

#define T_TOK 8192
#define DM 1024
#define DFF 4096
#define NE 8
#define MAXROWS 17408   // 2*8192 + 8*128 padding
#define MT 128          // M rows per CTA
#define BN 256          // N cols per CTA
#define BK 32           // K per stage

#define A_PAD 36                    // floats per A row in smem
#define B_PAD 264                   // floats per B row in smem
#define A_STAGE_F (128 * A_PAD)     // 4608
#define B_STAGE_F (32 * B_PAD)      // 8448
#define STAGE_F (A_STAGE_F + B_STAGE_F)  // 13056 floats = 52224 B
#define NSTAGE 3
#define SMEM_DYN (512 + NSTAGE * STAGE_F * 4)   // 157,184 B

// ---------------- scratch (static device globals; no allocations) ----------------
__device__ float g_h[(size_t)MAXROWS * DFF];    // GEMM1 output (gelu), fp32
__device__ float g_y2[(size_t)MAXROWS * DM];    // GEMM2 output (gated), fp32
__device__ int   g_counts[NE];
__device__ int   g_cursor[NE];
__device__ int   g_off[NE];
__device__ int   g_tiles[NE];
__device__ int   g_topk_e[T_TOK * 2];
__device__ float g_topk_p[T_TOK * 2];
__device__ int   g_rowmap[MAXROWS];
__device__ float g_rowgate[MAXROWS];
__device__ int   g_pos[T_TOK * 2];

// ---------------- helpers ----------------
__device__ __forceinline__ void cp_async16(uint32_t dst, const void* src, int srcbytes) {
    asm volatile("cp.async.cg.shared.global [%0], [%1], 16, %2;\n"
                 :: "r"(dst), "l"(src), "r"(srcbytes));
}

// jax.nn.gelu default: approximate=True (tanh form)
__device__ __forceinline__ float gelu_f(float v) {
    float c = 0.7978845608028654f * (v + 0.044715f * v * v * v);
    return 0.5f * v * (1.0f + tanhf(c));
}

// ---------------- K0: zero counters ----------------
__global__ void zero_kernel() {
    int i = threadIdx.x;
    if (i < NE) { g_counts[i] = 0; g_cursor[i] = 0; }
}

// ---------------- K1: router (1 warp per token) ----------------
__global__ void __launch_bounds__(256) router_kernel(
    const float* __restrict__ x, const float* __restrict__ rw, const float* __restrict__ rb)
{
    int t = (blockIdx.x * blockDim.x + threadIdx.x) >> 5;
    int lane = threadIdx.x & 31;
    if (t >= T_TOK) return;
    const float* xr = x + (size_t)t * DM;
    float acc[NE];
    #pragma unroll
    for (int e = 0; e < NE; e++) acc[e] = 0.f;
    for (int k = lane; k < DM; k += 32) {
        float xv = xr[k];
        const float4* w4 = (const float4*)(rw + (size_t)k * NE);
        float4 wa = w4[0], wb = w4[1];
        acc[0] += xv * wa.x; acc[1] += xv * wa.y; acc[2] += xv * wa.z; acc[3] += xv * wa.w;
        acc[4] += xv * wb.x; acc[5] += xv * wb.y; acc[6] += xv * wb.z; acc[7] += xv * wb.w;
    }
    #pragma unroll
    for (int off = 16; off > 0; off >>= 1) {
        #pragma unroll
        for (int e = 0; e < NE; e++) acc[e] += __shfl_down_sync(0xffffffffu, acc[e], off);
    }
    if (lane == 0) {
        float logit[NE], m = -1e30f;
        #pragma unroll
        for (int e = 0; e < NE; e++) { logit[e] = acc[e] + rb[e]; m = fmaxf(m, logit[e]); }
        float s = 0.f, p[NE];
        #pragma unroll
        for (int e = 0; e < NE; e++) { p[e] = expf(logit[e] - m); s += p[e]; }
        float inv = 1.0f / s;
        #pragma unroll
        for (int e = 0; e < NE; e++) p[e] *= inv;
        int i1 = 0;
        #pragma unroll
        for (int e = 1; e < NE; e++) if (p[e] > p[i1]) i1 = e;
        int i2 = (i1 == 0) ? 1 : 0;
        #pragma unroll
        for (int e = 0; e < NE; e++) { if (e == i1) continue; if (p[e] > p[i2]) i2 = e; }
        g_topk_e[t * 2] = i1; g_topk_e[t * 2 + 1] = i2;
        g_topk_p[t * 2] = p[i1]; g_topk_p[t * 2 + 1] = p[i2];
        atomicAdd(&g_counts[i1], 1);
        atomicAdd(&g_counts[i2], 1);
    }
}

// ---------------- K2: offsets + pad rowmap ----------------
__global__ void offsets_kernel() {
    __shared__ int soff[NE], scnt[NE], stiles[NE];
    if (threadIdx.x == 0) {
        int off = 0;
        for (int e = 0; e < NE; e++) {
            int c = g_counts[e];
            int tiles = (c + MT - 1) / MT;
            g_off[e] = off; g_tiles[e] = tiles;
            soff[e] = off; scnt[e] = c; stiles[e] = tiles;
            off += tiles * MT;
        }
    }
    __syncthreads();
    for (int e = 0; e < NE; e++) {
        int start = soff[e] + scnt[e];
        int end = soff[e] + stiles[e] * MT;
        for (int r = start + (int)threadIdx.x; r < end; r += blockDim.x) {
            g_rowmap[r] = -1;
            g_rowgate[r] = 0.f;
        }
    }
}

// ---------------- K3: slot assignment ----------------
__global__ void assign_kernel() {
    int t = blockIdx.x * blockDim.x + threadIdx.x;
    if (t >= T_TOK) return;
    #pragma unroll
    for (int k = 0; k < 2; k++) {
        int e = g_topk_e[t * 2 + k];
        int slot = atomicAdd(&g_cursor[e], 1);
        int r = g_off[e] + slot;
        g_rowmap[r] = t;
        g_rowgate[r] = g_topk_p[t * 2 + k];
        g_pos[t * 2 + k] = r;
    }
}

// ---------------- K4/K5: tf32 GEMM, 128x256 block / 64x64 warptile, 3-stage cp.async ----
// PHASE 1: gather(x) @ w1 + b1 -> gelu -> g_h      (K=1024, N=4096)
// PHASE 2: g_h @ w2 + b2, *gate -> g_y2            (K=4096, N=1024)
template <int PHASE>
__global__ void __launch_bounds__(256) moe_gemm_kernel(
    const float* __restrict__ Ain, const float* __restrict__ W, const float* __restrict__ bias)
{
    constexpr int KTOT = (PHASE == 1) ? DM : DFF;
    constexpr int NTOT = (PHASE == 1) ? DFF : DM;
    constexpr int NK = KTOT / BK;

    const int e = blockIdx.y >> 6;
    const int mt = blockIdx.y & 63;
    if (mt >= g_tiles[e]) return;
    const int nt = blockIdx.x;
    const int row0 = g_off[e] + mt * MT;

    extern __shared__ __align__(16) char dynbuf[];
    int*   rmap = (int*)dynbuf;                 // 128 ints
    float* sbuf = (float*)(dynbuf + 512);       // NSTAGE stages of [A|B]

    const int tid  = threadIdx.x;
    const int warp = tid >> 5;
    const int lane = tid & 31;
    const int g = lane >> 2;
    const int l = lane & 3;
    const int wm = warp >> 2;   // 0..1 : 64 rows each
    const int wn = warp & 3;    // 0..3 : 64 cols each

    if (PHASE == 1) {
        if (tid < MT) rmap[tid] = g_rowmap[row0 + tid];
    }
    __syncthreads();

    const float* Wb = W + (size_t)e * KTOT * NTOT + (size_t)nt * BN;

    // per-thread cp.async chunk setup: 4 A chunks + 8 B chunks (16B each)
    const char* asrc[4];
    uint32_t aoff[4];
    int asz[4];
    #pragma unroll
    for (int i = 0; i < 4; i++) {
        int idx = tid + i * 256;          // 0..1023
        int r  = idx >> 3;                // 0..127
        int kc = (idx & 7) << 2;          // 0..28
        if (PHASE == 1) {
            int s = rmap[r];
            asz[i]  = (s >= 0) ? 16 : 0;
            asrc[i] = (const char*)(Ain + (size_t)((s >= 0) ? s : 0) * DM + kc);
        } else {
            asz[i]  = 16;
            asrc[i] = (const char*)(g_h + (size_t)(row0 + r) * DFF + kc);
        }
        aoff[i] = (uint32_t)(r * A_PAD + kc) * 4u;
    }
    const char* bbase = (const char*)Wb;
    uint32_t bsrcoff[8], boff[8];
    #pragma unroll
    for (int i = 0; i < 8; i++) {
        int idx = tid + i * 256;          // 0..2047
        int kr = idx >> 6;                // 0..31
        int nc = (idx & 63) << 2;         // 0..252
        bsrcoff[i] = (uint32_t)(kr * NTOT + nc) * 4u;
        boff[i]    = (uint32_t)(A_STAGE_F + kr * B_PAD + nc) * 4u;
    }

    uint32_t sb = (uint32_t)__cvta_generic_to_shared(sbuf);

#define GEMM_ISSUE(J)                                                                 \
    do {                                                                              \
        uint32_t _sbase = sb + ((J) % NSTAGE) * (STAGE_F * 4);                        \
        size_t _akb = (size_t)(J) * (BK * 4);                                         \
        size_t _bkb = (size_t)(J) * ((size_t)BK * NTOT * 4);                          \
        _Pragma("unroll")                                                             \
        for (int i = 0; i < 4; i++)                                                   \
            cp_async16(_sbase + aoff[i], asrc[i] + _akb, asz[i]);                     \
        _Pragma("unroll")                                                             \
        for (int i = 0; i < 8; i++)                                                   \
            cp_async16(_sbase + boff[i], bbase + _bkb + bsrcoff[i], 16);              \
        asm volatile("cp.async.commit_group;\n" ::: "memory");                        \
    } while (0)

    float acc[4][8][4];
    #pragma unroll
    for (int a = 0; a < 4; a++)
        #pragma unroll
        for (int b = 0; b < 8; b++)
            #pragma unroll
            for (int c = 0; c < 4; c++) acc[a][b][c] = 0.f;

    GEMM_ISSUE(0);
    GEMM_ISSUE(1);

    for (int j = 0; j < NK; j++) {
        if (j < NK - 1) {
            asm volatile("cp.async.wait_group 1;\n" ::: "memory");
        } else {
            asm volatile("cp.async.wait_group 0;\n" ::: "memory");
        }
        __syncthreads();
        if (j + 2 < NK) GEMM_ISSUE(j + 2);

        const float* As = sbuf + (j % NSTAGE) * STAGE_F;
        const float* Bs = As + A_STAGE_F;

        #pragma unroll
        for (int ks = 0; ks < 4; ks++) {
            const int k0 = ks * 8;
            uint32_t afr[4][4];
            #pragma unroll
            for (int im = 0; im < 4; im++) {
                int mb = wm * 64 + im * 16;
                afr[im][0] = __float_as_uint(As[(mb + g) * A_PAD + k0 + l]);
                afr[im][1] = __float_as_uint(As[(mb + g + 8) * A_PAD + k0 + l]);
                afr[im][2] = __float_as_uint(As[(mb + g) * A_PAD + k0 + l + 4]);
                afr[im][3] = __float_as_uint(As[(mb + g + 8) * A_PAD + k0 + l + 4]);
            }
            #pragma unroll
            for (int in_ = 0; in_ < 8; in_++) {
                int nb = wn * 64 + in_ * 8;
                uint32_t b0 = __float_as_uint(Bs[(k0 + l) * B_PAD + nb + g]);
                uint32_t b1 = __float_as_uint(Bs[(k0 + l + 4) * B_PAD + nb + g]);
                #pragma unroll
                for (int im = 0; im < 4; im++) {
                    asm volatile(
                        "mma.sync.aligned.m16n8k8.row.col.f32.tf32.tf32.f32 "
                        "{%0,%1,%2,%3},{%4,%5,%6,%7},{%8,%9},{%0,%1,%2,%3};"
                        : "+f"(acc[im][in_][0]), "+f"(acc[im][in_][1]),
                          "+f"(acc[im][in_][2]), "+f"(acc[im][in_][3])
                        : "r"(afr[im][0]), "r"(afr[im][1]), "r"(afr[im][2]), "r"(afr[im][3]),
                          "r"(b0), "r"(b1));
                }
            }
        }
    }
#undef GEMM_ISSUE

    // ---- epilogue: direct float2 stores (rows g / g+8, cols 2l..2l+1) ----
    const float* biasE = bias + (size_t)e * NTOT;
    #pragma unroll
    for (int im = 0; im < 4; im++) {
        int lrow0 = wm * 64 + im * 16 + g;
        int grow0 = row0 + lrow0;
        int grow1 = grow0 + 8;
        float gate0 = 0.f, gate1 = 0.f;
        if (PHASE == 2) { gate0 = g_rowgate[grow0]; gate1 = g_rowgate[grow1]; }
        float* orow0 = (PHASE == 1) ? (g_h + (size_t)grow0 * DFF) : (g_y2 + (size_t)grow0 * DM);
        float* orow1 = (PHASE == 1) ? (g_h + (size_t)grow1 * DFF) : (g_y2 + (size_t)grow1 * DM);
        #pragma unroll
        for (int in_ = 0; in_ < 8; in_++) {
            int col = nt * BN + wn * 64 + in_ * 8 + 2 * l;
            float2 bv = *(const float2*)&biasE[col];
            float2 v0, v1;
            if (PHASE == 1) {
                v0.x = gelu_f(acc[im][in_][0] + bv.x);
                v0.y = gelu_f(acc[im][in_][1] + bv.y);
                v1.x = gelu_f(acc[im][in_][2] + bv.x);
                v1.y = gelu_f(acc[im][in_][3] + bv.y);
            } else {
                v0.x = gate0 * (acc[im][in_][0] + bv.x);
                v0.y = gate0 * (acc[im][in_][1] + bv.y);
                v1.x = gate1 * (acc[im][in_][2] + bv.x);
                v1.y = gate1 * (acc[im][in_][3] + bv.y);
            }
            *(float2*)&orow0[col] = v0;
            *(float2*)&orow1[col] = v1;
        }
    }
}

// ---------------- K6: combine + residual + LayerNorm ----------------
__global__ void __launch_bounds__(256) combine_ln_kernel(
    const float* __restrict__ x, const float* __restrict__ gamma,
    const float* __restrict__ beta, float* __restrict__ out, int out_size)
{
    int t = blockIdx.x;
    int tid = threadIdx.x;
    __shared__ float red[18];
    int p0 = g_pos[t * 2], p1 = g_pos[t * 2 + 1];
    float4 xv = ((const float4*)(x + (size_t)t * DM))[tid];
    float4 av = ((const float4*)(g_y2 + (size_t)p0 * DM))[tid];
    float4 bv = ((const float4*)(g_y2 + (size_t)p1 * DM))[tid];
    float4 y;
    y.x = xv.x + av.x + bv.x;
    y.y = xv.y + av.y + bv.y;
    y.z = xv.z + av.z + bv.z;
    y.w = xv.w + av.w + bv.w;
    float s  = y.x + y.y + y.z + y.w;
    float ss = y.x * y.x + y.y * y.y + y.z * y.z + y.w * y.w;
    #pragma unroll
    for (int o = 16; o > 0; o >>= 1) {
        s  += __shfl_down_sync(0xffffffffu, s, o);
        ss += __shfl_down_sync(0xffffffffu, ss, o);
    }
    int warp = tid >> 5, lane = tid & 31;
    if (lane == 0) { red[warp] = s; red[8 + warp] = ss; }
    __syncthreads();
    if (tid == 0) {
        float S = 0.f, SS = 0.f;
        #pragma unroll
        for (int w = 0; w < 8; w++) { S += red[w]; SS += red[8 + w]; }
        red[16] = S; red[17] = SS;
    }
    __syncthreads();
    float mu = red[16] * (1.0f / 1024.0f);
    float var = red[17] * (1.0f / 1024.0f) - mu * mu;
    float rs = rsqrtf(var + 1e-5f);
    float4 g4 = ((const float4*)gamma)[tid];
    float4 b4 = ((const float4*)beta)[tid];
    float4 z;
    z.x = (y.x - mu) * rs * g4.x + b4.x;
    z.y = (y.y - mu) * rs * g4.y + b4.y;
    z.z = (y.z - mu) * rs * g4.z + b4.z;
    z.w = (y.w - mu) * rs * g4.w + b4.w;
    if ((size_t)t * DM + (size_t)tid * 4 + 4 <= (size_t)out_size)
        ((float4*)(out + (size_t)t * DM))[tid] = z;
}

// ---------------- K7: "selected" export tail (if harness expects it) ----------------
__global__ void selected_kernel(float* __restrict__ out, int extras) {
    int i = blockIdx.x * blockDim.x + threadIdx.x;
    if (i < extras) {
        float v = (i < NE && g_counts[i] > 0) ? 1.0f : 0.0f;
        out[(size_t)T_TOK * DM + i] = v;
    }
}

// ---------------- launch ----------------
extern "C" void kernel_launch(void* const* d_in, const int* in_sizes, int n_in,
                              void* d_out, int out_size)
{
    const float* x     = (const float*)d_in[0];
    const float* rw    = (const float*)d_in[1];
    const float* rb    = (const float*)d_in[2];
    const float* w1    = (const float*)d_in[3];
    const float* b1    = (const float*)d_in[4];
    const float* w2    = (const float*)d_in[5];
    const float* b2    = (const float*)d_in[6];
    const float* gamma = (const float*)d_in[7];
    const float* beta  = (const float*)d_in[8];
    float* out = (float*)d_out;

    cudaFuncSetAttribute(moe_gemm_kernel<1>, cudaFuncAttributeMaxDynamicSharedMemorySize, SMEM_DYN);
    cudaFuncSetAttribute(moe_gemm_kernel<2>, cudaFuncAttributeMaxDynamicSharedMemorySize, SMEM_DYN);

    zero_kernel<<<1, 32>>>();
    router_kernel<<<T_TOK / 8, 256>>>(x, rw, rb);
    offsets_kernel<<<1, 256>>>();
    assign_kernel<<<T_TOK / 256, 256>>>();
    moe_gemm_kernel<1><<<dim3(DFF / BN, NE * 64), 256, SMEM_DYN>>>(x, w1, b1);
    moe_gemm_kernel<2><<<dim3(DM / BN, NE * 64), 256, SMEM_DYN>>>(nullptr, w2, b2);
    combine_ln_kernel<<<T_TOK, 256>>>(x, gamma, beta, out, out_size);
    int extras = out_size - T_TOK * DM;
    if (extras > 0) {
        selected_kernel<<<(extras + 255) / 256, 256>>>(out, extras);
    }
}

// round 13
// speedup vs baseline: 2.0118x; 1.3526x over previous
#include <cuda_runtime.h>
#include <cuda_fp16.h>
#include <math.h>
#include <stdint.h>

#define T_TOK 8192
#define DM 1024
#define DFF 4096
#define NE 8
#define MAXROWS 17408   // 2*8192 + 8*128 padding
#define MT 128          // M rows per CTA
#define BN 256          // N cols per CTA
#define BK 32           // K per stage

// smem: A 128 rows x 80B (32 halves + 8 pad), B 256 rows x 80B
#define A_ROW_B 80
#define A_STAGE_B (128 * A_ROW_B)        // 10240
#define B_STAGE_B (256 * A_ROW_B)        // 20480
#define STAGE_B (A_STAGE_B + B_STAGE_B)  // 30720
#define NSTAGE 3
#define SMEM_DYN (512 + NSTAGE * STAGE_B)  // 92,672 B

// ---------------- scratch (static device globals; no allocations) ----------------
__device__ __half g_h  [(size_t)MAXROWS * DFF];  // GEMM1 output (gelu), fp16
__device__ float  g_y2 [(size_t)MAXROWS * DM];   // GEMM2 output (gated), fp32
__device__ __half g_xh [(size_t)T_TOK * DM];     // x in fp16
__device__ __half g_w1t[(size_t)NE * DFF * DM];  // w1 fp16 transposed: [e][n][k]
__device__ __half g_w2t[(size_t)NE * DM * DFF];  // w2 fp16 transposed: [e][n][k]
__device__ int    g_counts[NE];
__device__ int    g_cursor[NE];
__device__ int    g_off[NE];
__device__ int    g_tiles[NE];
__device__ int    g_topk_e[T_TOK * 2];
__device__ float  g_topk_p[T_TOK * 2];
__device__ int    g_rowmap[MAXROWS];
__device__ float  g_rowgate[MAXROWS];
__device__ int    g_pos[T_TOK * 2];

// ---------------- helpers ----------------
__device__ __forceinline__ void cp_async16(uint32_t dst, const void* src, int srcbytes) {
    asm volatile("cp.async.cg.shared.global [%0], [%1], 16, %2;\n"
                 :: "r"(dst), "l"(src), "r"(srcbytes));
}

// jax.nn.gelu default: approximate=True (tanh form)
__device__ __forceinline__ float gelu_f(float v) {
    float c = 0.7978845608028654f * (v + 0.044715f * v * v * v);
    return 0.5f * v * (1.0f + tanhf(c));
}

// ---------------- K0: zero counters ----------------
__global__ void zero_kernel() {
    int i = threadIdx.x;
    if (i < NE) { g_counts[i] = 0; g_cursor[i] = 0; }
}

// ---------------- K1: router (1 warp per token) ----------------
__global__ void __launch_bounds__(256) router_kernel(
    const float* __restrict__ x, const float* __restrict__ rw, const float* __restrict__ rb)
{
    int t = (blockIdx.x * blockDim.x + threadIdx.x) >> 5;
    int lane = threadIdx.x & 31;
    if (t >= T_TOK) return;
    const float* xr = x + (size_t)t * DM;
    float acc[NE];
    #pragma unroll
    for (int e = 0; e < NE; e++) acc[e] = 0.f;
    for (int k = lane; k < DM; k += 32) {
        float xv = xr[k];
        const float4* w4 = (const float4*)(rw + (size_t)k * NE);
        float4 wa = w4[0], wb = w4[1];
        acc[0] += xv * wa.x; acc[1] += xv * wa.y; acc[2] += xv * wa.z; acc[3] += xv * wa.w;
        acc[4] += xv * wb.x; acc[5] += xv * wb.y; acc[6] += xv * wb.z; acc[7] += xv * wb.w;
    }
    #pragma unroll
    for (int off = 16; off > 0; off >>= 1) {
        #pragma unroll
        for (int e = 0; e < NE; e++) acc[e] += __shfl_down_sync(0xffffffffu, acc[e], off);
    }
    if (lane == 0) {
        float logit[NE], m = -1e30f;
        #pragma unroll
        for (int e = 0; e < NE; e++) { logit[e] = acc[e] + rb[e]; m = fmaxf(m, logit[e]); }
        float s = 0.f, p[NE];
        #pragma unroll
        for (int e = 0; e < NE; e++) { p[e] = expf(logit[e] - m); s += p[e]; }
        float inv = 1.0f / s;
        #pragma unroll
        for (int e = 0; e < NE; e++) p[e] *= inv;
        int i1 = 0;
        #pragma unroll
        for (int e = 1; e < NE; e++) if (p[e] > p[i1]) i1 = e;
        int i2 = (i1 == 0) ? 1 : 0;
        #pragma unroll
        for (int e = 0; e < NE; e++) { if (e == i1) continue; if (p[e] > p[i2]) i2 = e; }
        g_topk_e[t * 2] = i1; g_topk_e[t * 2 + 1] = i2;
        g_topk_p[t * 2] = p[i1]; g_topk_p[t * 2 + 1] = p[i2];
        atomicAdd(&g_counts[i1], 1);
        atomicAdd(&g_counts[i2], 1);
    }
}

// ---------------- K2: offsets + pad rowmap ----------------
__global__ void offsets_kernel() {
    __shared__ int soff[NE], scnt[NE], stiles[NE];
    if (threadIdx.x == 0) {
        int off = 0;
        for (int e = 0; e < NE; e++) {
            int c = g_counts[e];
            int tiles = (c + MT - 1) / MT;
            g_off[e] = off; g_tiles[e] = tiles;
            soff[e] = off; scnt[e] = c; stiles[e] = tiles;
            off += tiles * MT;
        }
    }
    __syncthreads();
    for (int e = 0; e < NE; e++) {
        int start = soff[e] + scnt[e];
        int end = soff[e] + stiles[e] * MT;
        for (int r = start + (int)threadIdx.x; r < end; r += blockDim.x) {
            g_rowmap[r] = -1;
            g_rowgate[r] = 0.f;
        }
    }
}

// ---------------- K3: slot assignment ----------------
__global__ void assign_kernel() {
    int t = blockIdx.x * blockDim.x + threadIdx.x;
    if (t >= T_TOK) return;
    #pragma unroll
    for (int k = 0; k < 2; k++) {
        int e = g_topk_e[t * 2 + k];
        int slot = atomicAdd(&g_cursor[e], 1);
        int r = g_off[e] + slot;
        g_rowmap[r] = t;
        g_rowgate[r] = g_topk_p[t * 2 + k];
        g_pos[t * 2 + k] = r;
    }
}

// ---------------- K3b: x -> fp16 ----------------
__global__ void __launch_bounds__(256) cvt_x_kernel(const float* __restrict__ x) {
    int i = blockIdx.x * blockDim.x + threadIdx.x;   // element/4 index
    float4 v = ((const float4*)x)[i];
    __half2 h0 = __floats2half2_rn(v.x, v.y);
    __half2 h1 = __floats2half2_rn(v.z, v.w);
    ((uint2*)g_xh)[i] = make_uint2(*(uint32_t*)&h0, *(uint32_t*)&h1);
}

// ---------------- K3c: weight convert+transpose  src fp32 [e][R][C] -> dst fp16 [e][C][R] ----
__global__ void __launch_bounds__(256) cvtT_w_kernel(
    const float* __restrict__ src, __half* __restrict__ dst, int R, int C)
{
    __shared__ float sh[32][33];
    int e = blockIdx.z;
    const float* s = src + (size_t)e * R * C;
    __half* d = dst + (size_t)e * R * C;
    int c0 = blockIdx.x * 32, r0 = blockIdx.y * 32;
    int tx = threadIdx.x, ty = threadIdx.y;
    #pragma unroll
    for (int i = 0; i < 4; i++)
        sh[ty + i * 8][tx] = s[(size_t)(r0 + ty + i * 8) * C + c0 + tx];
    __syncthreads();
    #pragma unroll
    for (int i = 0; i < 4; i++)
        d[(size_t)(c0 + ty + i * 8) * R + r0 + tx] = __float2half(sh[tx][ty + i * 8]);
}

// ---------------- K4/K5: fp16 GEMM, 128x256 block / 64x32 warptile / 512 thr / 3-stage ----
// PHASE 1: gather(xh) @ w1t + b1 -> gelu -> g_h (fp16)   (K=1024, N=4096)
// PHASE 2: g_h @ w2t + b2, *gate -> g_y2 (fp32)          (K=4096, N=1024)
template <int PHASE>
__global__ void __launch_bounds__(512, 1) moe_gemm_kernel(
    const __half* __restrict__ Wt, const float* __restrict__ bias)
{
    constexpr int KTOT = (PHASE == 1) ? DM : DFF;
    constexpr int NTOT = (PHASE == 1) ? DFF : DM;
    constexpr int NK = KTOT / BK;

    const int e = blockIdx.y >> 6;
    const int mt = blockIdx.y & 63;
    if (mt >= g_tiles[e]) return;
    const int nt = blockIdx.x;
    const int row0 = g_off[e] + mt * MT;

    extern __shared__ __align__(16) char dynbuf[];
    int*  rmap = (int*)dynbuf;                 // 128 ints
    char* sbuf = dynbuf + 512;                 // NSTAGE stages of [A|B]

    const int tid  = threadIdx.x;
    const int warp = tid >> 5;
    const int lane = tid & 31;
    const int g = lane >> 2;
    const int l = lane & 3;
    const int wm = warp >> 3;   // 0..1 : 64 rows each
    const int wn = warp & 7;    // 0..7 : 32 cols each

    if (PHASE == 1) {
        if (tid < MT) rmap[tid] = g_rowmap[row0 + tid];
    }
    __syncthreads();

    // per-thread cp.async setup: 1 A chunk + 2 B chunks (16B each)
    const char* asrc;
    uint32_t aoffb;
    int asz;
    {
        int r = tid >> 2;          // 0..127
        int c = tid & 3;           // 16B chunk in row
        if (PHASE == 1) {
            int s = rmap[r];
            asz  = (s >= 0) ? 16 : 0;
            asrc = (const char*)(g_xh + (size_t)((s >= 0) ? s : 0) * DM) + c * 16;
        } else {
            asz  = 16;
            asrc = (const char*)(g_h + (size_t)(row0 + r) * DFF) + c * 16;
        }
        aoffb = (uint32_t)(r * A_ROW_B + c * 16);
    }
    const char* bsrc[2];
    uint32_t boffb[2];
    #pragma unroll
    for (int i = 0; i < 2; i++) {
        int idx = tid + i * 512;   // 0..1023
        int n = idx >> 2;          // 0..255
        int c = idx & 3;
        bsrc[i]  = (const char*)(Wt + ((size_t)e * NTOT + (size_t)nt * BN + n) * KTOT) + c * 16;
        boffb[i] = (uint32_t)(A_STAGE_B + n * A_ROW_B + c * 16);
    }

    uint32_t sb = (uint32_t)__cvta_generic_to_shared(sbuf);

#define GEMM_ISSUE(J)                                                                 \
    do {                                                                              \
        uint32_t _sbase = sb + ((J) % NSTAGE) * STAGE_B;                              \
        size_t _kb = (size_t)(J) * 64;   /* 32 halves per ktile */                    \
        cp_async16(_sbase + aoffb, asrc + _kb, asz);                                  \
        cp_async16(_sbase + boffb[0], bsrc[0] + _kb, 16);                             \
        cp_async16(_sbase + boffb[1], bsrc[1] + _kb, 16);                             \
        asm volatile("cp.async.commit_group;\n" ::: "memory");                        \
    } while (0)

    float acc[4][4][4];
    #pragma unroll
    for (int a = 0; a < 4; a++)
        #pragma unroll
        for (int b = 0; b < 4; b++)
            #pragma unroll
            for (int c = 0; c < 4; c++) acc[a][b][c] = 0.f;

    GEMM_ISSUE(0);
    GEMM_ISSUE(1);

    for (int j = 0; j < NK; j++) {
        if (j < NK - 1) {
            asm volatile("cp.async.wait_group 1;\n" ::: "memory");
        } else {
            asm volatile("cp.async.wait_group 0;\n" ::: "memory");
        }
        __syncthreads();
        if (j + 2 < NK) GEMM_ISSUE(j + 2);

        const char* As = sbuf + (j % NSTAGE) * STAGE_B;
        const char* Bs = As + A_STAGE_B;

        #pragma unroll
        for (int ks = 0; ks < 2; ks++) {
            const int kb = ks * 32;   // byte offset of 16-half k-step
            uint32_t afr[4][4];
            #pragma unroll
            for (int im = 0; im < 4; im++) {
                int rbase = (wm * 64 + im * 16 + g) * A_ROW_B + kb + l * 4;
                afr[im][0] = *(const uint32_t*)(As + rbase);
                afr[im][1] = *(const uint32_t*)(As + rbase + 8 * A_ROW_B);
                afr[im][2] = *(const uint32_t*)(As + rbase + 16);
                afr[im][3] = *(const uint32_t*)(As + rbase + 8 * A_ROW_B + 16);
            }
            #pragma unroll
            for (int in_ = 0; in_ < 4; in_++) {
                int nbase = (wn * 32 + in_ * 8 + g) * A_ROW_B + kb + l * 4;
                uint32_t b0 = *(const uint32_t*)(Bs + nbase);
                uint32_t b1 = *(const uint32_t*)(Bs + nbase + 16);
                #pragma unroll
                for (int im = 0; im < 4; im++) {
                    asm volatile(
                        "mma.sync.aligned.m16n8k16.row.col.f32.f16.f16.f32 "
                        "{%0,%1,%2,%3},{%4,%5,%6,%7},{%8,%9},{%0,%1,%2,%3};"
                        : "+f"(acc[im][in_][0]), "+f"(acc[im][in_][1]),
                          "+f"(acc[im][in_][2]), "+f"(acc[im][in_][3])
                        : "r"(afr[im][0]), "r"(afr[im][1]), "r"(afr[im][2]), "r"(afr[im][3]),
                          "r"(b0), "r"(b1));
                }
            }
        }
    }
#undef GEMM_ISSUE

    // ---- epilogue: rows g / g+8, cols 2l..2l+1 ----
    const float* biasE = bias + (size_t)e * NTOT;
    #pragma unroll
    for (int im = 0; im < 4; im++) {
        int lrow0 = wm * 64 + im * 16 + g;
        int grow0 = row0 + lrow0;
        int grow1 = grow0 + 8;
        float gate0 = 0.f, gate1 = 0.f;
        if (PHASE == 2) { gate0 = g_rowgate[grow0]; gate1 = g_rowgate[grow1]; }
        #pragma unroll
        for (int in_ = 0; in_ < 4; in_++) {
            int col = nt * BN + wn * 32 + in_ * 8 + 2 * l;
            float2 bv = *(const float2*)&biasE[col];
            if (PHASE == 1) {
                float h00 = gelu_f(acc[im][in_][0] + bv.x);
                float h01 = gelu_f(acc[im][in_][1] + bv.y);
                float h10 = gelu_f(acc[im][in_][2] + bv.x);
                float h11 = gelu_f(acc[im][in_][3] + bv.y);
                __half2 p0 = __floats2half2_rn(h00, h01);
                __half2 p1 = __floats2half2_rn(h10, h11);
                *(__half2*)(g_h + (size_t)grow0 * DFF + col) = p0;
                *(__half2*)(g_h + (size_t)grow1 * DFF + col) = p1;
            } else {
                float2 v0, v1;
                v0.x = gate0 * (acc[im][in_][0] + bv.x);
                v0.y = gate0 * (acc[im][in_][1] + bv.y);
                v1.x = gate1 * (acc[im][in_][2] + bv.x);
                v1.y = gate1 * (acc[im][in_][3] + bv.y);
                *(float2*)(g_y2 + (size_t)grow0 * DM + col) = v0;
                *(float2*)(g_y2 + (size_t)grow1 * DM + col) = v1;
            }
        }
    }
}

// ---------------- K6: combine + residual + LayerNorm ----------------
__global__ void __launch_bounds__(256) combine_ln_kernel(
    const float* __restrict__ x, const float* __restrict__ gamma,
    const float* __restrict__ beta, float* __restrict__ out, int out_size)
{
    int t = blockIdx.x;
    int tid = threadIdx.x;
    __shared__ float red[18];
    int p0 = g_pos[t * 2], p1 = g_pos[t * 2 + 1];
    float4 xv = ((const float4*)(x + (size_t)t * DM))[tid];
    float4 av = ((const float4*)(g_y2 + (size_t)p0 * DM))[tid];
    float4 bv = ((const float4*)(g_y2 + (size_t)p1 * DM))[tid];
    float4 y;
    y.x = xv.x + av.x + bv.x;
    y.y = xv.y + av.y + bv.y;
    y.z = xv.z + av.z + bv.z;
    y.w = xv.w + av.w + bv.w;
    float s  = y.x + y.y + y.z + y.w;
    float ss = y.x * y.x + y.y * y.y + y.z * y.z + y.w * y.w;
    #pragma unroll
    for (int o = 16; o > 0; o >>= 1) {
        s  += __shfl_down_sync(0xffffffffu, s, o);
        ss += __shfl_down_sync(0xffffffffu, ss, o);
    }
    int warp = tid >> 5, lane = tid & 31;
    if (lane == 0) { red[warp] = s; red[8 + warp] = ss; }
    __syncthreads();
    if (tid == 0) {
        float S = 0.f, SS = 0.f;
        #pragma unroll
        for (int w = 0; w < 8; w++) { S += red[w]; SS += red[8 + w]; }
        red[16] = S; red[17] = SS;
    }
    __syncthreads();
    float mu = red[16] * (1.0f / 1024.0f);
    float var = red[17] * (1.0f / 1024.0f) - mu * mu;
    float rs = rsqrtf(var + 1e-5f);
    float4 g4 = ((const float4*)gamma)[tid];
    float4 b4 = ((const float4*)beta)[tid];
    float4 z;
    z.x = (y.x - mu) * rs * g4.x + b4.x;
    z.y = (y.y - mu) * rs * g4.y + b4.y;
    z.z = (y.z - mu) * rs * g4.z + b4.z;
    z.w = (y.w - mu) * rs * g4.w + b4.w;
    if ((size_t)t * DM + (size_t)tid * 4 + 4 <= (size_t)out_size)
        ((float4*)(out + (size_t)t * DM))[tid] = z;
}

// ---------------- K7: "selected" export tail (if harness expects it) ----------------
__global__ void selected_kernel(float* __restrict__ out, int extras) {
    int i = blockIdx.x * blockDim.x + threadIdx.x;
    if (i < extras) {
        float v = (i < NE && g_counts[i] > 0) ? 1.0f : 0.0f;
        out[(size_t)T_TOK * DM + i] = v;
    }
}

// ---------------- launch ----------------
extern "C" void kernel_launch(void* const* d_in, const int* in_sizes, int n_in,
                              void* d_out, int out_size)
{
    const float* x     = (const float*)d_in[0];
    const float* rw    = (const float*)d_in[1];
    const float* rb    = (const float*)d_in[2];
    const float* w1    = (const float*)d_in[3];
    const float* b1    = (const float*)d_in[4];
    const float* w2    = (const float*)d_in[5];
    const float* b2    = (const float*)d_in[6];
    const float* gamma = (const float*)d_in[7];
    const float* beta  = (const float*)d_in[8];
    float* out = (float*)d_out;

    cudaFuncSetAttribute(moe_gemm_kernel<1>, cudaFuncAttributeMaxDynamicSharedMemorySize, SMEM_DYN);
    cudaFuncSetAttribute(moe_gemm_kernel<2>, cudaFuncAttributeMaxDynamicSharedMemorySize, SMEM_DYN);

    __half* w1t; cudaGetSymbolAddress((void**)&w1t, g_w1t);
    __half* w2t; cudaGetSymbolAddress((void**)&w2t, g_w2t);

    zero_kernel<<<1, 32>>>();
    router_kernel<<<T_TOK / 8, 256>>>(x, rw, rb);
    offsets_kernel<<<1, 256>>>();
    assign_kernel<<<T_TOK / 256, 256>>>();
    cvt_x_kernel<<<T_TOK * DM / 4 / 256, 256>>>(x);
    // w1 [e][1024][4096] -> w1t [e][4096][1024]; w2 [e][4096][1024] -> w2t [e][1024][4096]
    cvtT_w_kernel<<<dim3(DFF / 32, DM / 32, NE), dim3(32, 8)>>>(w1, w1t, DM, DFF);
    cvtT_w_kernel<<<dim3(DM / 32, DFF / 32, NE), dim3(32, 8)>>>(w2, w2t, DFF, DM);
    moe_gemm_kernel<1><<<dim3(DFF / BN, NE * 64), 512, SMEM_DYN>>>(w1t, b1);
    moe_gemm_kernel<2><<<dim3(DM / BN, NE * 64), 512, SMEM_DYN>>>(w2t, b2);
    combine_ln_kernel<<<T_TOK, 256>>>(x, gamma, beta, out, out_size);
    int extras = out_size - T_TOK * DM;
    if (extras > 0) {
        selected_kernel<<<(extras + 255) / 256, 256>>>(out, extras);
    }
}

// round 15
// speedup vs baseline: 2.3290x; 1.1577x over previous
#include <cuda_runtime.h>
#include <cuda_fp16.h>
#include <math.h>
#include <stdint.h>

#define T_TOK 8192
#define DM 1024
#define DFF 4096
#define NE 8
#define MAXROWS 17408   // 2*8192 + 8*128 padding
#define MT 128          // M rows per CTA
#define BN 256          // N cols per CTA
#define BK 64           // K per stage

// smem: A 128 rows x 144B (64 halves + 16B pad), B 256 rows x 144B
#define A_ROW_B 144
#define A_STAGE_B (128 * A_ROW_B)        // 18432
#define B_STAGE_B (256 * A_ROW_B)        // 36864
#define STAGE_B (A_STAGE_B + B_STAGE_B)  // 55296
#define NSTAGE 3
#define SMEM_DYN (512 + NSTAGE * STAGE_B)  // 166,400 B

// ---------------- scratch (static device globals; no allocations) ----------------
__device__ __half g_h  [(size_t)MAXROWS * DFF];  // GEMM1 output (gelu), fp16
__device__ float  g_y2 [(size_t)MAXROWS * DM];   // GEMM2 output (gated), fp32
__device__ __half g_xh [(size_t)T_TOK * DM];     // x in fp16
__device__ __half g_w1t[(size_t)NE * DFF * DM];  // w1 fp16 transposed: [e][n][k]
__device__ __half g_w2t[(size_t)NE * DM * DFF];  // w2 fp16 transposed: [e][n][k]
__device__ int    g_counts[NE];
__device__ int    g_cursor[NE];
__device__ int    g_off[NE];
__device__ int    g_tiles[NE];
__device__ int    g_topk_e[T_TOK * 2];
__device__ float  g_topk_p[T_TOK * 2];
__device__ int    g_rowmap[MAXROWS];
__device__ float  g_rowgate[MAXROWS];
__device__ int    g_pos[T_TOK * 2];

// ---------------- helpers ----------------
__device__ __forceinline__ void cp_async16(uint32_t dst, const void* src, int srcbytes) {
    asm volatile("cp.async.cg.shared.global [%0], [%1], 16, %2;\n"
                 :: "r"(dst), "l"(src), "r"(srcbytes));
}

// jax.nn.gelu default: approximate=True (tanh form)
__device__ __forceinline__ float gelu_f(float v) {
    float c = 0.7978845608028654f * (v + 0.044715f * v * v * v);
    return 0.5f * v * (1.0f + tanhf(c));
}

// ---------------- K0: zero counters ----------------
__global__ void zero_kernel() {
    int i = threadIdx.x;
    if (i < NE) { g_counts[i] = 0; g_cursor[i] = 0; }
}

// ---------------- K1: router (1 warp per token) + x->fp16 conversion ----------------
__global__ void __launch_bounds__(256) router_kernel(
    const float* __restrict__ x, const float* __restrict__ rw, const float* __restrict__ rb)
{
    int t = (blockIdx.x * blockDim.x + threadIdx.x) >> 5;
    int lane = threadIdx.x & 31;
    if (t >= T_TOK) return;
    const float4* xr4 = (const float4*)(x + (size_t)t * DM);
    uint2* xh2 = (uint2*)(g_xh + (size_t)t * DM);
    const float4* w4 = (const float4*)rw;
    float acc[NE];
    #pragma unroll
    for (int e = 0; e < NE; e++) acc[e] = 0.f;
    for (int k4 = lane; k4 < DM / 4; k4 += 32) {
        float4 v = xr4[k4];
        __half2 h0 = __floats2half2_rn(v.x, v.y);
        __half2 h1 = __floats2half2_rn(v.z, v.w);
        xh2[k4] = make_uint2(*(uint32_t*)&h0, *(uint32_t*)&h1);
        int k = k4 * 4;
        #pragma unroll
        for (int j = 0; j < 4; j++) {
            float xv = (&v.x)[j];
            float4 wa = w4[(k + j) * 2], wb = w4[(k + j) * 2 + 1];
            acc[0] += xv * wa.x; acc[1] += xv * wa.y; acc[2] += xv * wa.z; acc[3] += xv * wa.w;
            acc[4] += xv * wb.x; acc[5] += xv * wb.y; acc[6] += xv * wb.z; acc[7] += xv * wb.w;
        }
    }
    #pragma unroll
    for (int off = 16; off > 0; off >>= 1) {
        #pragma unroll
        for (int e = 0; e < NE; e++) acc[e] += __shfl_down_sync(0xffffffffu, acc[e], off);
    }
    if (lane == 0) {
        float logit[NE], m = -1e30f;
        #pragma unroll
        for (int e = 0; e < NE; e++) { logit[e] = acc[e] + rb[e]; m = fmaxf(m, logit[e]); }
        float s = 0.f, p[NE];
        #pragma unroll
        for (int e = 0; e < NE; e++) { p[e] = expf(logit[e] - m); s += p[e]; }
        float inv = 1.0f / s;
        #pragma unroll
        for (int e = 0; e < NE; e++) p[e] *= inv;
        int i1 = 0;
        #pragma unroll
        for (int e = 1; e < NE; e++) if (p[e] > p[i1]) i1 = e;
        int i2 = (i1 == 0) ? 1 : 0;
        #pragma unroll
        for (int e = 0; e < NE; e++) { if (e == i1) continue; if (p[e] > p[i2]) i2 = e; }
        g_topk_e[t * 2] = i1; g_topk_e[t * 2 + 1] = i2;
        g_topk_p[t * 2] = p[i1]; g_topk_p[t * 2 + 1] = p[i2];
        atomicAdd(&g_counts[i1], 1);
        atomicAdd(&g_counts[i2], 1);
    }
}

// ---------------- K2: offsets + pad rowmap ----------------
__global__ void offsets_kernel() {
    __shared__ int soff[NE], scnt[NE], stiles[NE];
    if (threadIdx.x == 0) {
        int off = 0;
        for (int e = 0; e < NE; e++) {
            int c = g_counts[e];
            int tiles = (c + MT - 1) / MT;
            g_off[e] = off; g_tiles[e] = tiles;
            soff[e] = off; scnt[e] = c; stiles[e] = tiles;
            off += tiles * MT;
        }
    }
    __syncthreads();
    for (int e = 0; e < NE; e++) {
        int start = soff[e] + scnt[e];
        int end = soff[e] + stiles[e] * MT;
        for (int r = start + (int)threadIdx.x; r < end; r += blockDim.x) {
            g_rowmap[r] = -1;
            g_rowgate[r] = 0.f;
        }
    }
}

// ---------------- K3: slot assignment ----------------
__global__ void assign_kernel() {
    int t = blockIdx.x * blockDim.x + threadIdx.x;
    if (t >= T_TOK) return;
    #pragma unroll
    for (int k = 0; k < 2; k++) {
        int e = g_topk_e[t * 2 + k];
        int slot = atomicAdd(&g_cursor[e], 1);
        int r = g_off[e] + slot;
        g_rowmap[r] = t;
        g_rowgate[r] = g_topk_p[t * 2 + k];
        g_pos[t * 2 + k] = r;
    }
}

// ---------------- K3b: weight convert+transpose  src fp32 [e][R][C] -> dst fp16 [e][C][R] ----
__global__ void __launch_bounds__(256) cvtT_w_kernel(
    const float* __restrict__ src, __half* __restrict__ dst, int R, int C)
{
    __shared__ float sh[32][33];
    int e = blockIdx.z;
    const float* s = src + (size_t)e * R * C;
    __half* d = dst + (size_t)e * R * C;
    int c0 = blockIdx.x * 32, r0 = blockIdx.y * 32;
    int tx = threadIdx.x, ty = threadIdx.y;
    #pragma unroll
    for (int i = 0; i < 4; i++)
        sh[ty + i * 8][tx] = s[(size_t)(r0 + ty + i * 8) * C + c0 + tx];
    __syncthreads();
    #pragma unroll
    for (int i = 0; i < 4; i++)
        d[(size_t)(c0 + ty + i * 8) * R + r0 + tx] = __float2half(sh[tx][ty + i * 8]);
}

// ---------------- K4/K5: fp16 GEMM, 128x256 block / 64x32 warptile / 512 thr / 3-stage BK=64 ----
// PHASE 1: gather(xh) @ w1t + b1 -> gelu -> g_h (fp16)   (K=1024, N=4096)
// PHASE 2: g_h @ w2t + b2, *gate -> g_y2 (fp32)          (K=4096, N=1024)
template <int PHASE>
__global__ void __launch_bounds__(512, 1) moe_gemm_kernel(
    const __half* __restrict__ Wt, const float* __restrict__ bias)
{
    constexpr int KTOT = (PHASE == 1) ? DM : DFF;
    constexpr int NTOT = (PHASE == 1) ? DFF : DM;
    constexpr int NK = KTOT / BK;

    const int e = blockIdx.y >> 6;
    const int mt = blockIdx.y & 63;
    if (mt >= g_tiles[e]) return;
    const int nt = blockIdx.x;
    const int row0 = g_off[e] + mt * MT;

    extern __shared__ __align__(16) char dynbuf[];
    int*  rmap = (int*)dynbuf;                 // 128 ints
    char* sbuf = dynbuf + 512;                 // NSTAGE stages of [A|B]

    const int tid  = threadIdx.x;
    const int warp = tid >> 5;
    const int lane = tid & 31;
    const int g = lane >> 2;
    const int l = lane & 3;
    const int wm = warp >> 3;   // 0..1 : 64 rows each
    const int wn = warp & 7;    // 0..7 : 32 cols each

    if (PHASE == 1) {
        if (tid < MT) rmap[tid] = g_rowmap[row0 + tid];
    }
    __syncthreads();

    // per-thread cp.async setup: 2 A chunks + 4 B chunks (16B each)
    const char* asrc[2];
    uint32_t aoffb[2];
    int asz[2];
    #pragma unroll
    for (int i = 0; i < 2; i++) {
        int idx = tid + i * 512;   // 0..1023
        int r = idx >> 3;          // 0..127
        int c = idx & 7;           // 16B chunk in 128B k-window
        if (PHASE == 1) {
            int s = rmap[r];
            asz[i]  = (s >= 0) ? 16 : 0;
            asrc[i] = (const char*)(g_xh + (size_t)((s >= 0) ? s : 0) * DM) + c * 16;
        } else {
            asz[i]  = 16;
            asrc[i] = (const char*)(g_h + (size_t)(row0 + r) * DFF) + c * 16;
        }
        aoffb[i] = (uint32_t)(r * A_ROW_B + c * 16);
    }
    const char* bsrc[4];
    uint32_t boffb[4];
    #pragma unroll
    for (int i = 0; i < 4; i++) {
        int idx = tid + i * 512;   // 0..2047
        int n = idx >> 3;          // 0..255
        int c = idx & 7;
        bsrc[i]  = (const char*)(Wt + ((size_t)e * NTOT + (size_t)nt * BN + n) * KTOT) + c * 16;
        boffb[i] = (uint32_t)(A_STAGE_B + n * A_ROW_B + c * 16);
    }

    uint32_t sb = (uint32_t)__cvta_generic_to_shared(sbuf);

#define GEMM_ISSUE(J)                                                                 \
    do {                                                                              \
        uint32_t _sbase = sb + ((J) % NSTAGE) * STAGE_B;                              \
        size_t _kb = (size_t)(J) * 128;   /* 64 halves per ktile */                   \
        cp_async16(_sbase + aoffb[0], asrc[0] + _kb, asz[0]);                         \
        cp_async16(_sbase + aoffb[1], asrc[1] + _kb, asz[1]);                         \
        cp_async16(_sbase + boffb[0], bsrc[0] + _kb, 16);                             \
        cp_async16(_sbase + boffb[1], bsrc[1] + _kb, 16);                             \
        cp_async16(_sbase + boffb[2], bsrc[2] + _kb, 16);                             \
        cp_async16(_sbase + boffb[3], bsrc[3] + _kb, 16);                             \
        asm volatile("cp.async.commit_group;\n" ::: "memory");                        \
    } while (0)

    float acc[4][4][4];
    #pragma unroll
    for (int a = 0; a < 4; a++)
        #pragma unroll
        for (int b = 0; b < 4; b++)
            #pragma unroll
            for (int c = 0; c < 4; c++) acc[a][b][c] = 0.f;

    GEMM_ISSUE(0);
    GEMM_ISSUE(1);

    for (int j = 0; j < NK; j++) {
        if (j < NK - 1) {
            asm volatile("cp.async.wait_group 1;\n" ::: "memory");
        } else {
            asm volatile("cp.async.wait_group 0;\n" ::: "memory");
        }
        __syncthreads();
        if (j + 2 < NK) GEMM_ISSUE(j + 2);

        const char* As = sbuf + (j % NSTAGE) * STAGE_B;
        const char* Bs = As + A_STAGE_B;

        #pragma unroll
        for (int ks = 0; ks < 4; ks++) {
            const int kb = ks * 32;   // byte offset of 16-half k-step
            uint32_t afr[4][4];
            #pragma unroll
            for (int im = 0; im < 4; im++) {
                int rbase = (wm * 64 + im * 16 + g) * A_ROW_B + kb + l * 4;
                afr[im][0] = *(const uint32_t*)(As + rbase);
                afr[im][1] = *(const uint32_t*)(As + rbase + 8 * A_ROW_B);
                afr[im][2] = *(const uint32_t*)(As + rbase + 16);
                afr[im][3] = *(const uint32_t*)(As + rbase + 8 * A_ROW_B + 16);
            }
            #pragma unroll
            for (int in_ = 0; in_ < 4; in_++) {
                int nbase = (wn * 32 + in_ * 8 + g) * A_ROW_B + kb + l * 4;
                uint32_t b0 = *(const uint32_t*)(Bs + nbase);
                uint32_t b1 = *(const uint32_t*)(Bs + nbase + 16);
                #pragma unroll
                for (int im = 0; im < 4; im++) {
                    asm volatile(
                        "mma.sync.aligned.m16n8k16.row.col.f32.f16.f16.f32 "
                        "{%0,%1,%2,%3},{%4,%5,%6,%7},{%8,%9},{%0,%1,%2,%3};"
                        : "+f"(acc[im][in_][0]), "+f"(acc[im][in_][1]),
                          "+f"(acc[im][in_][2]), "+f"(acc[im][in_][3])
                        : "r"(afr[im][0]), "r"(afr[im][1]), "r"(afr[im][2]), "r"(afr[im][3]),
                          "r"(b0), "r"(b1));
                }
            }
        }
    }
#undef GEMM_ISSUE

    // ---- epilogue: rows g / g+8, cols 2l..2l+1 ----
    const float* biasE = bias + (size_t)e * NTOT;
    #pragma unroll
    for (int im = 0; im < 4; im++) {
        int lrow0 = wm * 64 + im * 16 + g;
        int grow0 = row0 + lrow0;
        int grow1 = grow0 + 8;
        float gate0 = 0.f, gate1 = 0.f;
        if (PHASE == 2) { gate0 = g_rowgate[grow0]; gate1 = g_rowgate[grow1]; }
        #pragma unroll
        for (int in_ = 0; in_ < 4; in_++) {
            int col = nt * BN + wn * 32 + in_ * 8 + 2 * l;
            float2 bv = *(const float2*)&biasE[col];
            if (PHASE == 1) {
                float h00 = gelu_f(acc[im][in_][0] + bv.x);
                float h01 = gelu_f(acc[im][in_][1] + bv.y);
                float h10 = gelu_f(acc[im][in_][2] + bv.x);
                float h11 = gelu_f(acc[im][in_][3] + bv.y);
                __half2 p0 = __floats2half2_rn(h00, h01);
                __half2 p1 = __floats2half2_rn(h10, h11);
                *(__half2*)(g_h + (size_t)grow0 * DFF + col) = p0;
                *(__half2*)(g_h + (size_t)grow1 * DFF + col) = p1;
            } else {
                float2 v0, v1;
                v0.x = gate0 * (acc[im][in_][0] + bv.x);
                v0.y = gate0 * (acc[im][in_][1] + bv.y);
                v1.x = gate1 * (acc[im][in_][2] + bv.x);
                v1.y = gate1 * (acc[im][in_][3] + bv.y);
                *(float2*)(g_y2 + (size_t)grow0 * DM + col) = v0;
                *(float2*)(g_y2 + (size_t)grow1 * DM + col) = v1;
            }
        }
    }
}

// ---------------- K6: combine + residual + LayerNorm ----------------
__global__ void __launch_bounds__(256) combine_ln_kernel(
    const float* __restrict__ x, const float* __restrict__ gamma,
    const float* __restrict__ beta, float* __restrict__ out, int out_size)
{
    int t = blockIdx.x;
    int tid = threadIdx.x;
    __shared__ float red[18];
    int p0 = g_pos[t * 2], p1 = g_pos[t * 2 + 1];
    float4 xv = ((const float4*)(x + (size_t)t * DM))[tid];
    float4 av = ((const float4*)(g_y2 + (size_t)p0 * DM))[tid];
    float4 bv = ((const float4*)(g_y2 + (size_t)p1 * DM))[tid];
    float4 y;
    y.x = xv.x + av.x + bv.x;
    y.y = xv.y + av.y + bv.y;
    y.z = xv.z + av.z + bv.z;
    y.w = xv.w + av.w + bv.w;
    float s  = y.x + y.y + y.z + y.w;
    float ss = y.x * y.x + y.y * y.y + y.z * y.z + y.w * y.w;
    #pragma unroll
    for (int o = 16; o > 0; o >>= 1) {
        s  += __shfl_down_sync(0xffffffffu, s, o);
        ss += __shfl_down_sync(0xffffffffu, ss, o);
    }
    int warp = tid >> 5, lane = tid & 31;
    if (lane == 0) { red[warp] = s; red[8 + warp] = ss; }
    __syncthreads();
    if (tid == 0) {
        float S = 0.f, SS = 0.f;
        #pragma unroll
        for (int w = 0; w < 8; w++) { S += red[w]; SS += red[8 + w]; }
        red[16] = S; red[17] = SS;
    }
    __syncthreads();
    float mu = red[16] * (1.0f / 1024.0f);
    float var = red[17] * (1.0f / 1024.0f) - mu * mu;
    float rs = rsqrtf(var + 1e-5f);
    float4 g4 = ((const float4*)gamma)[tid];
    float4 b4 = ((const float4*)beta)[tid];
    float4 z;
    z.x = (y.x - mu) * rs * g4.x + b4.x;
    z.y = (y.y - mu) * rs * g4.y + b4.y;
    z.z = (y.z - mu) * rs * g4.z + b4.z;
    z.w = (y.w - mu) * rs * g4.w + b4.w;
    if ((size_t)t * DM + (size_t)tid * 4 + 4 <= (size_t)out_size)
        ((float4*)(out + (size_t)t * DM))[tid] = z;
}

// ---------------- K7: "selected" export tail (if harness expects it) ----------------
__global__ void selected_kernel(float* __restrict__ out, int extras) {
    int i = blockIdx.x * blockDim.x + threadIdx.x;
    if (i < extras) {
        float v = (i < NE && g_counts[i] > 0) ? 1.0f : 0.0f;
        out[(size_t)T_TOK * DM + i] = v;
    }
}

// ---------------- launch ----------------
extern "C" void kernel_launch(void* const* d_in, const int* in_sizes, int n_in,
                              void* d_out, int out_size)
{
    const float* x     = (const float*)d_in[0];
    const float* rw    = (const float*)d_in[1];
    const float* rb    = (const float*)d_in[2];
    const float* w1    = (const float*)d_in[3];
    const float* b1    = (const float*)d_in[4];
    const float* w2    = (const float*)d_in[5];
    const float* b2    = (const float*)d_in[6];
    const float* gamma = (const float*)d_in[7];
    const float* beta  = (const float*)d_in[8];
    float* out = (float*)d_out;

    cudaFuncSetAttribute(moe_gemm_kernel<1>, cudaFuncAttributeMaxDynamicSharedMemorySize, SMEM_DYN);
    cudaFuncSetAttribute(moe_gemm_kernel<2>, cudaFuncAttributeMaxDynamicSharedMemorySize, SMEM_DYN);

    __half* w1t; cudaGetSymbolAddress((void**)&w1t, g_w1t);
    __half* w2t; cudaGetSymbolAddress((void**)&w2t, g_w2t);

    zero_kernel<<<1, 32>>>();
    router_kernel<<<T_TOK / 8, 256>>>(x, rw, rb);
    offsets_kernel<<<1, 256>>>();
    assign_kernel<<<T_TOK / 256, 256>>>();
    // w1 [e][1024][4096] -> w1t [e][4096][1024]; w2 [e][4096][1024] -> w2t [e][1024][4096]
    cvtT_w_kernel<<<dim3(DFF / 32, DM / 32, NE), dim3(32, 8)>>>(w1, w1t, DM, DFF);
    cvtT_w_kernel<<<dim3(DM / 32, DFF / 32, NE), dim3(32, 8)>>>(w2, w2t, DFF, DM);
    moe_gemm_kernel<1><<<dim3(DFF / BN, NE * 64), 512, SMEM_DYN>>>(w1t, b1);
    moe_gemm_kernel<2><<<dim3(DM / BN, NE * 64), 512, SMEM_DYN>>>(w2t, b2);
    combine_ln_kernel<<<T_TOK, 256>>>(x, gamma, beta, out, out_size);
    int extras = out_size - T_TOK * DM;
    if (extras > 0) {
        selected_kernel<<<(extras + 255) / 256, 256>>>(out, extras);
    }
}

// round 16
// speedup vs baseline: 2.4119x; 1.0356x over previous
#include <cuda_runtime.h>
#include <cuda_fp16.h>
#include <math.h>
#include <stdint.h>

#define T_TOK 8192
#define DM 1024
#define DFF 4096
#define NE 8
#define MAXROWS 17408   // 2*8192 + 8*128 padding
#define MT 128          // M rows per CTA
#define BN 256          // N cols per CTA
#define BK 128          // K per stage

// smem: A 128 rows x 272B (128 halves + 16B pad), B 256 rows x 272B
#define A_ROW_B 272
#define A_STAGE_B (128 * A_ROW_B)        // 34816
#define B_STAGE_B (256 * A_ROW_B)        // 69632
#define STAGE_B (A_STAGE_B + B_STAGE_B)  // 104448
#define NSTAGE 2
#define SMEM_DYN (512 + NSTAGE * STAGE_B)  // 209,408 B

#define KSPLIT 2048     // GEMM2 K per split

// ---------------- scratch (static device globals; no allocations) ----------------
__device__ __half g_h  [(size_t)MAXROWS * DFF];  // GEMM1 output (gelu), fp16
__device__ float  g_y2 [(size_t)MAXROWS * DM];   // GEMM2 split-0 partial (gated)
__device__ float  g_y2b[(size_t)MAXROWS * DM];   // GEMM2 split-1 partial (gated, +bias)
__device__ __half g_xh [(size_t)T_TOK * DM];     // x in fp16
__device__ __half g_w1t[(size_t)NE * DFF * DM];  // w1 fp16 transposed: [e][n][k]
__device__ __half g_w2t[(size_t)NE * DM * DFF];  // w2 fp16 transposed: [e][n][k]
__device__ int    g_counts[NE];
__device__ int    g_cursor[NE];
__device__ int    g_off[NE];
__device__ int    g_tiles[NE];
__device__ int    g_topk_e[T_TOK * 2];
__device__ float  g_topk_p[T_TOK * 2];
__device__ int    g_rowmap[MAXROWS];
__device__ float  g_rowgate[MAXROWS];
__device__ int    g_pos[T_TOK * 2];

// ---------------- helpers ----------------
__device__ __forceinline__ void cp_async16(uint32_t dst, const void* src, int srcbytes) {
    asm volatile("cp.async.cg.shared.global [%0], [%1], 16, %2;\n"
                 :: "r"(dst), "l"(src), "r"(srcbytes));
}

// jax.nn.gelu default: approximate=True (tanh form)
__device__ __forceinline__ float gelu_f(float v) {
    float c = 0.7978845608028654f * (v + 0.044715f * v * v * v);
    return 0.5f * v * (1.0f + tanhf(c));
}

// ---------------- K0: zero counters ----------------
__global__ void zero_kernel() {
    int i = threadIdx.x;
    if (i < NE) { g_counts[i] = 0; g_cursor[i] = 0; }
}

// ---------------- K1: router (1 warp per token) + x->fp16 conversion ----------------
__global__ void __launch_bounds__(256) router_kernel(
    const float* __restrict__ x, const float* __restrict__ rw, const float* __restrict__ rb)
{
    int t = (blockIdx.x * blockDim.x + threadIdx.x) >> 5;
    int lane = threadIdx.x & 31;
    if (t >= T_TOK) return;
    const float4* xr4 = (const float4*)(x + (size_t)t * DM);
    uint2* xh2 = (uint2*)(g_xh + (size_t)t * DM);
    const float4* w4 = (const float4*)rw;
    float acc[NE];
    #pragma unroll
    for (int e = 0; e < NE; e++) acc[e] = 0.f;
    for (int k4 = lane; k4 < DM / 4; k4 += 32) {
        float4 v = xr4[k4];
        __half2 h0 = __floats2half2_rn(v.x, v.y);
        __half2 h1 = __floats2half2_rn(v.z, v.w);
        xh2[k4] = make_uint2(*(uint32_t*)&h0, *(uint32_t*)&h1);
        int k = k4 * 4;
        #pragma unroll
        for (int j = 0; j < 4; j++) {
            float xv = (&v.x)[j];
            float4 wa = w4[(k + j) * 2], wb = w4[(k + j) * 2 + 1];
            acc[0] += xv * wa.x; acc[1] += xv * wa.y; acc[2] += xv * wa.z; acc[3] += xv * wa.w;
            acc[4] += xv * wb.x; acc[5] += xv * wb.y; acc[6] += xv * wb.z; acc[7] += xv * wb.w;
        }
    }
    #pragma unroll
    for (int off = 16; off > 0; off >>= 1) {
        #pragma unroll
        for (int e = 0; e < NE; e++) acc[e] += __shfl_down_sync(0xffffffffu, acc[e], off);
    }
    if (lane == 0) {
        float logit[NE], m = -1e30f;
        #pragma unroll
        for (int e = 0; e < NE; e++) { logit[e] = acc[e] + rb[e]; m = fmaxf(m, logit[e]); }
        float s = 0.f, p[NE];
        #pragma unroll
        for (int e = 0; e < NE; e++) { p[e] = expf(logit[e] - m); s += p[e]; }
        float inv = 1.0f / s;
        #pragma unroll
        for (int e = 0; e < NE; e++) p[e] *= inv;
        int i1 = 0;
        #pragma unroll
        for (int e = 1; e < NE; e++) if (p[e] > p[i1]) i1 = e;
        int i2 = (i1 == 0) ? 1 : 0;
        #pragma unroll
        for (int e = 0; e < NE; e++) { if (e == i1) continue; if (p[e] > p[i2]) i2 = e; }
        g_topk_e[t * 2] = i1; g_topk_e[t * 2 + 1] = i2;
        g_topk_p[t * 2] = p[i1]; g_topk_p[t * 2 + 1] = p[i2];
        atomicAdd(&g_counts[i1], 1);
        atomicAdd(&g_counts[i2], 1);
    }
}

// ---------------- K2: offsets + pad rowmap ----------------
__global__ void offsets_kernel() {
    __shared__ int soff[NE], scnt[NE], stiles[NE];
    if (threadIdx.x == 0) {
        int off = 0;
        for (int e = 0; e < NE; e++) {
            int c = g_counts[e];
            int tiles = (c + MT - 1) / MT;
            g_off[e] = off; g_tiles[e] = tiles;
            soff[e] = off; scnt[e] = c; stiles[e] = tiles;
            off += tiles * MT;
        }
    }
    __syncthreads();
    for (int e = 0; e < NE; e++) {
        int start = soff[e] + scnt[e];
        int end = soff[e] + stiles[e] * MT;
        for (int r = start + (int)threadIdx.x; r < end; r += blockDim.x) {
            g_rowmap[r] = -1;
            g_rowgate[r] = 0.f;
        }
    }
}

// ---------------- K3: slot assignment ----------------
__global__ void assign_kernel() {
    int t = blockIdx.x * blockDim.x + threadIdx.x;
    if (t >= T_TOK) return;
    #pragma unroll
    for (int k = 0; k < 2; k++) {
        int e = g_topk_e[t * 2 + k];
        int slot = atomicAdd(&g_cursor[e], 1);
        int r = g_off[e] + slot;
        g_rowmap[r] = t;
        g_rowgate[r] = g_topk_p[t * 2 + k];
        g_pos[t * 2 + k] = r;
    }
}

// ---------------- K3b: weight convert+transpose  src fp32 [e][R][C] -> dst fp16 [e][C][R] ----
__global__ void __launch_bounds__(256) cvtT_w_kernel(
    const float* __restrict__ src, __half* __restrict__ dst, int R, int C)
{
    __shared__ float sh[32][33];
    int e = blockIdx.z;
    const float* s = src + (size_t)e * R * C;
    __half* d = dst + (size_t)e * R * C;
    int c0 = blockIdx.x * 32, r0 = blockIdx.y * 32;
    int tx = threadIdx.x, ty = threadIdx.y;
    #pragma unroll
    for (int i = 0; i < 4; i++)
        sh[ty + i * 8][tx] = s[(size_t)(r0 + ty + i * 8) * C + c0 + tx];
    __syncthreads();
    #pragma unroll
    for (int i = 0; i < 4; i++)
        d[(size_t)(c0 + ty + i * 8) * R + r0 + tx] = __float2half(sh[tx][ty + i * 8]);
}

// ---------------- K4/K5: fp16 GEMM, 128x256 block / 64x32 warptile / 512 thr / 2-stage BK=128 ----
// PHASE 1: gather(xh) @ w1t + b1 -> gelu -> g_h (fp16)   (K=1024, N=4096)
// PHASE 2: g_h @ w2t, *gate -> split partials            (K=2048/split, N=1024)
//          split 0 -> g_y2 (gate*acc), split 1 -> g_y2b (gate*(acc+bias))
template <int PHASE>
__global__ void __launch_bounds__(512, 1) moe_gemm_kernel(
    const __half* __restrict__ Wt, const float* __restrict__ bias)
{
    constexpr int KTOT = (PHASE == 1) ? DM : KSPLIT;
    constexpr int KFULL = (PHASE == 1) ? DM : DFF;
    constexpr int NTOT = (PHASE == 1) ? DFF : DM;
    constexpr int NK = KTOT / BK;

    const int e = blockIdx.y >> 6;
    const int mt = blockIdx.y & 63;
    if (mt >= g_tiles[e]) return;
    const int nt = blockIdx.x;
    const int split = (PHASE == 2) ? blockIdx.z : 0;
    const int k0g = split * KSPLIT;     // k offset of this split
    const int row0 = g_off[e] + mt * MT;

    extern __shared__ __align__(16) char dynbuf[];
    int*  rmap = (int*)dynbuf;                 // 128 ints
    char* sbuf = dynbuf + 512;                 // NSTAGE stages of [A|B]

    const int tid  = threadIdx.x;
    const int warp = tid >> 5;
    const int lane = tid & 31;
    const int g = lane >> 2;
    const int l = lane & 3;
    const int wm = warp >> 3;   // 0..1 : 64 rows each
    const int wn = warp & 7;    // 0..7 : 32 cols each

    if (PHASE == 1) {
        if (tid < MT) rmap[tid] = g_rowmap[row0 + tid];
    }
    __syncthreads();

    // per-thread cp.async setup: 4 A chunks + 8 B chunks (16B each)
    const char* asrc[4];
    uint32_t aoffb[4];
    int asz[4];
    #pragma unroll
    for (int i = 0; i < 4; i++) {
        int idx = tid + i * 512;   // 0..2047
        int r = idx >> 4;          // 0..127
        int c = idx & 15;          // 16B chunk in 256B k-window
        if (PHASE == 1) {
            int s = rmap[r];
            asz[i]  = (s >= 0) ? 16 : 0;
            asrc[i] = (const char*)(g_xh + (size_t)((s >= 0) ? s : 0) * DM) + c * 16;
        } else {
            asz[i]  = 16;
            asrc[i] = (const char*)(g_h + (size_t)(row0 + r) * DFF + k0g) + c * 16;
        }
        aoffb[i] = (uint32_t)(r * A_ROW_B + c * 16);
    }
    const char* bsrc[8];
    uint32_t boffb[8];
    #pragma unroll
    for (int i = 0; i < 8; i++) {
        int idx = tid + i * 512;   // 0..4095
        int n = idx >> 4;          // 0..255
        int c = idx & 15;
        bsrc[i]  = (const char*)(Wt + ((size_t)e * NTOT + (size_t)nt * BN + n) * KFULL + k0g) + c * 16;
        boffb[i] = (uint32_t)(A_STAGE_B + n * A_ROW_B + c * 16);
    }

    uint32_t sb = (uint32_t)__cvta_generic_to_shared(sbuf);

#define GEMM_ISSUE(J)                                                                 \
    do {                                                                              \
        uint32_t _sbase = sb + ((J) & 1) * STAGE_B;                                   \
        size_t _kb = (size_t)(J) * 256;   /* 128 halves per ktile */                  \
        cp_async16(_sbase + aoffb[0], asrc[0] + _kb, asz[0]);                         \
        cp_async16(_sbase + aoffb[1], asrc[1] + _kb, asz[1]);                         \
        cp_async16(_sbase + aoffb[2], asrc[2] + _kb, asz[2]);                         \
        cp_async16(_sbase + aoffb[3], asrc[3] + _kb, asz[3]);                         \
        cp_async16(_sbase + boffb[0], bsrc[0] + _kb, 16);                             \
        cp_async16(_sbase + boffb[1], bsrc[1] + _kb, 16);                             \
        cp_async16(_sbase + boffb[2], bsrc[2] + _kb, 16);                             \
        cp_async16(_sbase + boffb[3], bsrc[3] + _kb, 16);                             \
        cp_async16(_sbase + boffb[4], bsrc[4] + _kb, 16);                             \
        cp_async16(_sbase + boffb[5], bsrc[5] + _kb, 16);                             \
        cp_async16(_sbase + boffb[6], bsrc[6] + _kb, 16);                             \
        cp_async16(_sbase + boffb[7], bsrc[7] + _kb, 16);                             \
        asm volatile("cp.async.commit_group;\n" ::: "memory");                        \
    } while (0)

    float acc[4][4][4];
    #pragma unroll
    for (int a = 0; a < 4; a++)
        #pragma unroll
        for (int b = 0; b < 4; b++)
            #pragma unroll
            for (int c = 0; c < 4; c++) acc[a][b][c] = 0.f;

    GEMM_ISSUE(0);

    for (int j = 0; j < NK; j++) {
        asm volatile("cp.async.wait_group 0;\n" ::: "memory");
        __syncthreads();
        if (j + 1 < NK) GEMM_ISSUE(j + 1);

        const char* As = sbuf + (j & 1) * STAGE_B;
        const char* Bs = As + A_STAGE_B;

        #pragma unroll
        for (int ks = 0; ks < 8; ks++) {
            const int kb = ks * 32;   // byte offset of 16-half k-step
            uint32_t afr[4][4];
            #pragma unroll
            for (int im = 0; im < 4; im++) {
                int rbase = (wm * 64 + im * 16 + g) * A_ROW_B + kb + l * 4;
                afr[im][0] = *(const uint32_t*)(As + rbase);
                afr[im][1] = *(const uint32_t*)(As + rbase + 8 * A_ROW_B);
                afr[im][2] = *(const uint32_t*)(As + rbase + 16);
                afr[im][3] = *(const uint32_t*)(As + rbase + 8 * A_ROW_B + 16);
            }
            #pragma unroll
            for (int in_ = 0; in_ < 4; in_++) {
                int nbase = (wn * 32 + in_ * 8 + g) * A_ROW_B + kb + l * 4;
                uint32_t b0 = *(const uint32_t*)(Bs + nbase);
                uint32_t b1 = *(const uint32_t*)(Bs + nbase + 16);
                #pragma unroll
                for (int im = 0; im < 4; im++) {
                    asm volatile(
                        "mma.sync.aligned.m16n8k16.row.col.f32.f16.f16.f32 "
                        "{%0,%1,%2,%3},{%4,%5,%6,%7},{%8,%9},{%0,%1,%2,%3};"
                        : "+f"(acc[im][in_][0]), "+f"(acc[im][in_][1]),
                          "+f"(acc[im][in_][2]), "+f"(acc[im][in_][3])
                        : "r"(afr[im][0]), "r"(afr[im][1]), "r"(afr[im][2]), "r"(afr[im][3]),
                          "r"(b0), "r"(b1));
                }
            }
        }
    }
#undef GEMM_ISSUE

    // ---- epilogue: rows g / g+8, cols 2l..2l+1 ----
    const float* biasE = bias + (size_t)e * NTOT;
    #pragma unroll
    for (int im = 0; im < 4; im++) {
        int lrow0 = wm * 64 + im * 16 + g;
        int grow0 = row0 + lrow0;
        int grow1 = grow0 + 8;
        float gate0 = 0.f, gate1 = 0.f;
        if (PHASE == 2) { gate0 = g_rowgate[grow0]; gate1 = g_rowgate[grow1]; }
        #pragma unroll
        for (int in_ = 0; in_ < 4; in_++) {
            int col = nt * BN + wn * 32 + in_ * 8 + 2 * l;
            float2 bv = *(const float2*)&biasE[col];
            if (PHASE == 1) {
                float h00 = gelu_f(acc[im][in_][0] + bv.x);
                float h01 = gelu_f(acc[im][in_][1] + bv.y);
                float h10 = gelu_f(acc[im][in_][2] + bv.x);
                float h11 = gelu_f(acc[im][in_][3] + bv.y);
                __half2 p0 = __floats2half2_rn(h00, h01);
                __half2 p1 = __floats2half2_rn(h10, h11);
                *(__half2*)(g_h + (size_t)grow0 * DFF + col) = p0;
                *(__half2*)(g_h + (size_t)grow1 * DFF + col) = p1;
            } else {
                float* obuf = (split == 0) ? g_y2 : g_y2b;
                float bx = (split == 0) ? 0.f : bv.x;
                float by = (split == 0) ? 0.f : bv.y;
                float2 v0, v1;
                v0.x = gate0 * (acc[im][in_][0] + bx);
                v0.y = gate0 * (acc[im][in_][1] + by);
                v1.x = gate1 * (acc[im][in_][2] + bx);
                v1.y = gate1 * (acc[im][in_][3] + by);
                *(float2*)(obuf + (size_t)grow0 * DM + col) = v0;
                *(float2*)(obuf + (size_t)grow1 * DM + col) = v1;
            }
        }
    }
}

// ---------------- K6: combine + residual + LayerNorm ----------------
__global__ void __launch_bounds__(256) combine_ln_kernel(
    const float* __restrict__ x, const float* __restrict__ gamma,
    const float* __restrict__ beta, float* __restrict__ out, int out_size)
{
    int t = blockIdx.x;
    int tid = threadIdx.x;
    __shared__ float red[18];
    int p0 = g_pos[t * 2], p1 = g_pos[t * 2 + 1];
    float4 xv = ((const float4*)(x + (size_t)t * DM))[tid];
    float4 a0 = ((const float4*)(g_y2  + (size_t)p0 * DM))[tid];
    float4 a1 = ((const float4*)(g_y2b + (size_t)p0 * DM))[tid];
    float4 b0 = ((const float4*)(g_y2  + (size_t)p1 * DM))[tid];
    float4 b1 = ((const float4*)(g_y2b + (size_t)p1 * DM))[tid];
    float4 y;
    y.x = xv.x + (a0.x + a1.x) + (b0.x + b1.x);
    y.y = xv.y + (a0.y + a1.y) + (b0.y + b1.y);
    y.z = xv.z + (a0.z + a1.z) + (b0.z + b1.z);
    y.w = xv.w + (a0.w + a1.w) + (b0.w + b1.w);
    float s  = y.x + y.y + y.z + y.w;
    float ss = y.x * y.x + y.y * y.y + y.z * y.z + y.w * y.w;
    #pragma unroll
    for (int o = 16; o > 0; o >>= 1) {
        s  += __shfl_down_sync(0xffffffffu, s, o);
        ss += __shfl_down_sync(0xffffffffu, ss, o);
    }
    int warp = tid >> 5, lane = tid & 31;
    if (lane == 0) { red[warp] = s; red[8 + warp] = ss; }
    __syncthreads();
    if (tid == 0) {
        float S = 0.f, SS = 0.f;
        #pragma unroll
        for (int w = 0; w < 8; w++) { S += red[w]; SS += red[8 + w]; }
        red[16] = S; red[17] = SS;
    }
    __syncthreads();
    float mu = red[16] * (1.0f / 1024.0f);
    float var = red[17] * (1.0f / 1024.0f) - mu * mu;
    float rs = rsqrtf(var + 1e-5f);
    float4 g4 = ((const float4*)gamma)[tid];
    float4 b4 = ((const float4*)beta)[tid];
    float4 z;
    z.x = (y.x - mu) * rs * g4.x + b4.x;
    z.y = (y.y - mu) * rs * g4.y + b4.y;
    z.z = (y.z - mu) * rs * g4.z + b4.z;
    z.w = (y.w - mu) * rs * g4.w + b4.w;
    if ((size_t)t * DM + (size_t)tid * 4 + 4 <= (size_t)out_size)
        ((float4*)(out + (size_t)t * DM))[tid] = z;
}

// ---------------- K7: "selected" export tail (if harness expects it) ----------------
__global__ void selected_kernel(float* __restrict__ out, int extras) {
    int i = blockIdx.x * blockDim.x + threadIdx.x;
    if (i < extras) {
        float v = (i < NE && g_counts[i] > 0) ? 1.0f : 0.0f;
        out[(size_t)T_TOK * DM + i] = v;
    }
}

// ---------------- launch ----------------
extern "C" void kernel_launch(void* const* d_in, const int* in_sizes, int n_in,
                              void* d_out, int out_size)
{
    const float* x     = (const float*)d_in[0];
    const float* rw    = (const float*)d_in[1];
    const float* rb    = (const float*)d_in[2];
    const float* w1    = (const float*)d_in[3];
    const float* b1    = (const float*)d_in[4];
    const float* w2    = (const float*)d_in[5];
    const float* b2    = (const float*)d_in[6];
    const float* gamma = (const float*)d_in[7];
    const float* beta  = (const float*)d_in[8];
    float* out = (float*)d_out;

    cudaFuncSetAttribute(moe_gemm_kernel<1>, cudaFuncAttributeMaxDynamicSharedMemorySize, SMEM_DYN);
    cudaFuncSetAttribute(moe_gemm_kernel<2>, cudaFuncAttributeMaxDynamicSharedMemorySize, SMEM_DYN);

    __half* w1t; cudaGetSymbolAddress((void**)&w1t, g_w1t);
    __half* w2t; cudaGetSymbolAddress((void**)&w2t, g_w2t);

    zero_kernel<<<1, 32>>>();
    router_kernel<<<T_TOK / 8, 256>>>(x, rw, rb);
    offsets_kernel<<<1, 256>>>();
    assign_kernel<<<T_TOK / 256, 256>>>();
    // w1 [e][1024][4096] -> w1t [e][4096][1024]; w2 [e][4096][1024] -> w2t [e][1024][4096]
    cvtT_w_kernel<<<dim3(DFF / 32, DM / 32, NE), dim3(32, 8)>>>(w1, w1t, DM, DFF);
    cvtT_w_kernel<<<dim3(DM / 32, DFF / 32, NE), dim3(32, 8)>>>(w2, w2t, DFF, DM);
    moe_gemm_kernel<1><<<dim3(DFF / BN, NE * 64, 1), 512, SMEM_DYN>>>(w1t, b1);
    moe_gemm_kernel<2><<<dim3(DM / BN, NE * 64, 2), 512, SMEM_DYN>>>(w2t, b2);
    combine_ln_kernel<<<T_TOK, 256>>>(x, gamma, beta, out, out_size);
    int extras = out_size - T_TOK * DM;
    if (extras > 0) {
        selected_kernel<<<(extras + 255) / 256, 256>>>(out, extras);
    }
}